// round 10
// baseline (speedup 1.0000x reference)
#include <cuda_runtime.h>

#define BB 64
#define DD 12288
#define NL 32
#define HH 2048

__device__ float g_h1[BB*HH];
__device__ float g_z1[BB*NL];
__device__ float g_zn[BB];
__device__ float g_sp[BB];
__device__ float g_sp2[BB], g_sv2[BB];
__device__ float g_sigterm[NL*NL];
__device__ float g_C[HH*HH];
__device__ float g_m1[BB*HH];
__device__ float g_m2[BB*HH];
__device__ float g_h2[BB*HH];
__device__ float g_T[BB*NL*HH];
__device__ float g_P[BB*NL*NL];
__device__ float g_G2[BB*NL*NL];
__device__ float g_zs[BB*NL];
__device__ float g_logdet[BB], g_trinv[BB];
__device__ float g_delta[BB*DD];
__device__ float g_dsq[BB];
__device__ float g_v[BB*HH];
__device__ float g_t[BB*NL];

union F2U { float2 f; unsigned long long u; };
__device__ __forceinline__ float2 f2fma(float2 a, float2 b, float2 c) {
    F2U A, Bv, Cv, R; A.f = a; Bv.f = b; Cv.f = c;
    asm("fma.rn.f32x2 %0, %1, %2, %3;" : "=l"(R.u) : "l"(A.u), "l"(Bv.u), "l"(Cv.u));
    return R.f;
}

// device-side operand binding (NEVER pass __device__ symbols from host)
template<int SEL> __device__ __forceinline__ const float* bindA(const float* A) {
    if (SEL == 1) return g_h2;
    if (SEL == 2) return g_delta;
    return A;
}
template<int SEL> __device__ __forceinline__ float* bindC() {
    if (SEL == 0) return g_h1;
    if (SEL == 1) return g_delta;
    return g_v;
}

__global__ void zero_kernel() {
    int i = blockIdx.x*blockDim.x + threadIdx.x;
    int tot = gridDim.x*blockDim.x;
    for (int k=i;k<BB*HH;k+=tot) { g_h1[k]=0.f; g_v[k]=0.f; }
    for (size_t k=i;k<(size_t)HH*HH;k+=tot) g_C[k]=0.f;
    for (size_t k=i;k<(size_t)BB*DD;k+=tot) g_delta[k]=0.f;
    if (i<BB) g_dsq[i]=0.f;
}

// C[m][n] (+)= sum_k A[m*lda+k] * (BT ? B[n*ldb+k] : B[k*ldb+n])
template<int BM,int BN,int BK,int TM,int TN,bool BT,bool ACC,int ASEL,int CSEL>
__global__ __launch_bounds__((BM/TM)*(BN/TN))
void gemm_k(const float* __restrict__ Ain, const float* __restrict__ B,
            int lda, int ldb, int ldc, int kChunk) {
    const float* __restrict__ A = bindA<ASEL>(Ain);
    float* __restrict__ C = bindC<CSEL>();
    constexpr int THREADS = (BM/TM)*(BN/TN);
    __shared__ float As[BK][BM+4];
    __shared__ float Bs[BK][BN+4];
    const int tid = threadIdx.x;
    const int tx = tid % (BN/TN), ty = tid / (BN/TN);
    const int row0 = blockIdx.y*BM, col0 = blockIdx.x*BN;
    const int k0 = blockIdx.z*kChunk, k1 = k0 + kChunk;
    float2 acc[TM][TN/2];
    #pragma unroll
    for (int i=0;i<TM;i++)
        #pragma unroll
        for (int j=0;j<TN/2;j++) acc[i][j]=make_float2(0.f,0.f);
    for (int kb=k0; kb<k1; kb+=BK) {
        for (int i=tid;i<BM*BK;i+=THREADS) {
            int m=i/BK, kk=i%BK;
            As[kk][m] = A[(size_t)(row0+m)*lda + kb+kk];
        }
        if (!BT) {
            for (int i=tid;i<BK*BN;i+=THREADS) {
                int kk=i/BN, n=i%BN;
                Bs[kk][n] = B[(size_t)(kb+kk)*ldb + col0+n];
            }
        } else {
            for (int i=tid;i<BK*BN;i+=THREADS) {
                int n=i/BK, kk=i%BK;
                Bs[kk][n] = B[(size_t)(col0+n)*ldb + kb+kk];
            }
        }
        __syncthreads();
        #pragma unroll
        for (int kk=0;kk<BK;kk++) {
            float a[TM]; float2 bb[TN/2];
            #pragma unroll
            for (int i=0;i<TM;i++) a[i]=As[kk][ty*TM+i];
            #pragma unroll
            for (int j=0;j<TN/2;j++) bb[j]=*(const float2*)&Bs[kk][tx*TN+2*j];
            #pragma unroll
            for (int i=0;i<TM;i++) {
                float2 a2 = make_float2(a[i],a[i]);
                #pragma unroll
                for (int j=0;j<TN/2;j++) acc[i][j]=f2fma(a2,bb[j],acc[i][j]);
            }
        }
        __syncthreads();
    }
    #pragma unroll
    for (int i=0;i<TM;i++) {
        int gm = row0+ty*TM+i;
        #pragma unroll
        for (int j=0;j<TN/2;j++) {
            int gn = col0+tx*TN+2*j;
            if (ACC) {
                atomicAdd(&C[(size_t)gm*ldc+gn],   acc[i][j].x);
                atomicAdd(&C[(size_t)gm*ldc+gn+1], acc[i][j].y);
            } else {
                *(float2*)&C[(size_t)gm*ldc+gn] = acc[i][j];
            }
        }
    }
}

__global__ void relu_bias_kernel(const float* __restrict__ b1) {
    int i = blockIdx.x*blockDim.x + threadIdx.x;
    if (i < BB*HH) g_h1[i] = fmaxf(g_h1[i] + b1[i & (HH-1)], 0.f);
}

__global__ __launch_bounds__(256) void z1_kernel(const float* __restrict__ W2e, const float* __restrict__ b2e) {
    int b = blockIdx.x, tid = threadIdx.x;
    __shared__ float hrow[HH];
    __shared__ float red[8][NL];
    for (int i=tid;i<HH;i+=256) hrow[i]=g_h1[b*HH+i];
    __syncthreads();
    int n = tid & 31, s = tid >> 5;
    float acc=0.f;
    for (int h=s;h<HH;h+=8) acc = fmaf(hrow[h], W2e[h*NL+n], acc);
    red[s][n]=acc;
    __syncthreads();
    if (tid < NL) {
        float z = b2e[tid];
        #pragma unroll
        for (int ss=0;ss<8;ss++) z += red[ss][tid];
        g_z1[b*NL+tid]=z;
    }
}

__global__ void spsv_kernel(const float* __restrict__ sW, const float* __restrict__ sb) {
    int b = threadIdx.x;
    if (b >= BB) return;
    float a0=sb[0], zn=0.f;
    #pragma unroll
    for (int n=0;n<NL;n++) {
        float z = g_z1[b*NL+n];
        a0 = fmaf(z, sW[n*2], a0);
        zn = fmaf(z, z, zn);
    }
    g_sp[b]=expf(a0); g_zn[b]=zn;
}

__global__ void sigterm_kernel(const float* __restrict__ sW) {
    int i = threadIdx.x;
    int n = i >> 5, m = i & 31;
    g_sigterm[i] = 0.5f*((float)NL*sW[n*2]*sW[m*2] + (float)(DD-NL)*sW[n*2+1]*sW[m*2+1]);
}

// C = W2 W2^T, upper 128x128 tiles, split-K over blockIdx.y (atomic accumulate)
__global__ __launch_bounds__(256) void syrk_kernel(const float* __restrict__ W2, int kChunk) {
    int p = blockIdx.x, bi = 0, cnt = 16;
    while (p >= cnt) { p -= cnt; cnt--; bi++; }
    int bj = bi + p;
    const int k0 = blockIdx.y*kChunk, k1 = k0 + kChunk;
    __shared__ float As[16][132];
    __shared__ float Bs[16][132];
    const int tid = threadIdx.x, tx = tid & 15, ty = tid >> 4;
    const float* Arow = W2 + (size_t)bi*128*DD;
    const float* Brow = W2 + (size_t)bj*128*DD;
    float2 acc[8][4];
    #pragma unroll
    for (int i=0;i<8;i++)
        #pragma unroll
        for (int j=0;j<4;j++) acc[i][j]=make_float2(0.f,0.f);
    for (int kb=k0;kb<k1;kb+=16) {
        for (int i=tid;i<2048;i+=256) { int r=i>>4, c=i&15; As[c][r]=Arow[(size_t)r*DD+kb+c]; }
        for (int i=tid;i<2048;i+=256) { int r=i>>4, c=i&15; Bs[c][r]=Brow[(size_t)r*DD+kb+c]; }
        __syncthreads();
        #pragma unroll
        for (int kk=0;kk<16;kk++) {
            float4 a0=*(const float4*)&As[kk][ty*8], a1=*(const float4*)&As[kk][ty*8+4];
            float4 b0=*(const float4*)&Bs[kk][tx*8], b1=*(const float4*)&Bs[kk][tx*8+4];
            float av[8]={a0.x,a0.y,a0.z,a0.w,a1.x,a1.y,a1.z,a1.w};
            float2 bb[4]={{b0.x,b0.y},{b0.z,b0.w},{b1.x,b1.y},{b1.z,b1.w}};
            #pragma unroll
            for (int i=0;i<8;i++) {
                float2 a2 = make_float2(av[i],av[i]);
                #pragma unroll
                for (int j=0;j<4;j++) acc[i][j]=f2fma(a2,bb[j],acc[i][j]);
            }
        }
        __syncthreads();
    }
    #pragma unroll
    for (int i=0;i<8;i++) {
        int gi = bi*128 + ty*8 + i;
        #pragma unroll
        for (int j=0;j<4;j++) {
            int gj = bj*128 + tx*8 + 2*j;
            atomicAdd(&g_C[(size_t)gi*HH + gj],   acc[i][j].x);
            atomicAdd(&g_C[(size_t)gi*HH + gj+1], acc[i][j].y);
        }
    }
}

__global__ __launch_bounds__(1024) void mirror_kernel() {
    int p = blockIdx.x, ti = 0, cnt = 64;
    while (p >= cnt) { p -= cnt; cnt--; ti++; }
    int tj = ti + p;
    int tx = threadIdx.x & 31, ty = threadIdx.x >> 5;
    int i0 = ti*32, j0 = tj*32;
    if (ti == tj) {
        int i = i0+ty, j = j0+tx;
        if (j > i) g_C[(size_t)j*HH+i] = g_C[(size_t)i*HH+j];
    } else {
        __shared__ float tile[32][33];
        tile[ty][tx] = g_C[(size_t)(i0+ty)*HH + j0+tx];
        __syncthreads();
        g_C[(size_t)(j0+ty)*HH + i0+tx] = tile[tx][ty];
    }
}

__global__ __launch_bounds__(256) void dec_kernel(const float* __restrict__ W1, const float* __restrict__ b1, int useZs) {
    int b = blockIdx.y;
    int h = blockIdx.x*256 + threadIdx.x;
    __shared__ float zs[NL];
    if (threadIdx.x < NL) zs[threadIdx.x] = useZs ? g_zs[b*NL+threadIdx.x] : g_z1[b*NL+threadIdx.x];
    __syncthreads();
    float acc = b1[h];
    #pragma unroll
    for (int n=0;n<NL;n++) acc = fmaf(zs[n], W1[n*HH+h], acc);
    if (useZs) {
        g_m2[b*HH+h] = acc>0.f?1.f:0.f;
        g_h2[b*HH+h] = fmaxf(acc, 0.f);
    } else {
        g_m1[b*HH+h] = acc>0.f?1.f:0.f;
    }
}

__global__ __launch_bounds__(128) void t_gemm_kernel(const float* __restrict__ W1, int useM2) {
    int b = blockIdx.y;
    int col0 = blockIdx.x*128;
    const float* mrow = (useM2 ? g_m2 : g_m1) + b*HH;
    __shared__ float As[32][33];
    __shared__ float Bs[32][132];
    const int tid = threadIdx.x, tx = tid & 15, ty = tid >> 4;
    float2 acc[4][4];
    #pragma unroll
    for (int i=0;i<4;i++)
        #pragma unroll
        for (int j=0;j<4;j++) acc[i][j]=make_float2(0.f,0.f);
    for (int kb=0;kb<HH;kb+=32) {
        for (int i=tid;i<1024;i+=128) { int n=i>>5, kk=i&31; As[kk][n]=W1[n*HH+kb+kk]*mrow[kb+kk]; }
        for (int i=tid;i<4096;i+=128) { int kk=i>>7, n=i&127; Bs[kk][n]=g_C[(size_t)(kb+kk)*HH + col0+n]; }
        __syncthreads();
        #pragma unroll
        for (int kk=0;kk<32;kk++) {
            float a[4];
            #pragma unroll
            for (int i=0;i<4;i++) a[i]=As[kk][ty*4+i];
            float4 b0=*(const float4*)&Bs[kk][tx*8], b1=*(const float4*)&Bs[kk][tx*8+4];
            float2 bb[4]={{b0.x,b0.y},{b0.z,b0.w},{b1.x,b1.y},{b1.z,b1.w}};
            #pragma unroll
            for (int i=0;i<4;i++) {
                float2 a2=make_float2(a[i],a[i]);
                #pragma unroll
                for (int j=0;j<4;j++) acc[i][j]=f2fma(a2,bb[j],acc[i][j]);
            }
        }
        __syncthreads();
    }
    #pragma unroll
    for (int i=0;i<4;i++) {
        int n = ty*4+i;
        #pragma unroll
        for (int j=0;j<4;j++) {
            int c = col0 + tx*8 + 2*j;
            *(float2*)&g_T[(size_t)b*NL*HH + n*HH + c] = acc[i][j];
        }
    }
}

__global__ __launch_bounds__(1024) void g_kernel(const float* __restrict__ W1, int mode) {
    int b = blockIdx.x;
    int tx = threadIdx.x & 31, ty = threadIdx.x >> 5;
    const float* mrow = (mode ? g_m2 : g_m1) + b*HH;
    __shared__ float Ts[32][33], Ws[32][33];
    float acc = 0.f;
    for (int j0=0;j0<HH;j0+=32) {
        Ts[ty][tx] = g_T[(size_t)b*NL*HH + ty*HH + j0+tx];
        Ws[ty][tx] = W1[ty*HH + j0+tx]*mrow[j0+tx];
        __syncthreads();
        #pragma unroll
        for (int jj=0;jj<32;jj++) acc = fmaf(Ts[ty][jj], Ws[tx][jj], acc);
        __syncthreads();
    }
    if (mode == 0) {
        float sp = g_sp[b];
        float val = acc/(sp*sp) + g_sigterm[ty*NL+tx] + (tx==ty ? 1.f : 0.f);
        g_P[b*NL*NL + ty*NL + tx] = val;
    } else {
        g_G2[b*NL*NL + ty*NL + tx] = acc;
    }
}

__device__ void chol32_serial(float A[NL][NL]) {
    for (int k=0;k<NL;k++) {
        A[k][k] = sqrtf(A[k][k]);
        float inv = 1.f/A[k][k];
        for (int i=k+1;i<NL;i++) A[i][k] *= inv;
        for (int i=k+1;i<NL;i++) {
            float lik = A[i][k];
            for (int j=k+1;j<=i;j++) A[i][j] -= lik*A[j][k];
        }
    }
}

__global__ void chol_prec_kernel(const float* __restrict__ eps, const float* __restrict__ sW, const float* __restrict__ sb) {
    int b = blockIdx.x*blockDim.x + threadIdx.x;
    if (b >= BB) return;
    float A[NL][NL];
    for (int i=0;i<NL;i++)
        for (int j=0;j<=i;j++) A[i][j] = g_P[b*NL*NL + i*NL + j];
    chol32_serial(A);
    float ld = 0.f;
    for (int k=0;k<NL;k++) ld += logf(A[k][k]);
    float tr = 0.f;
    float X[NL];
    for (int c=0;c<NL;c++) {
        X[c] = 1.f/A[c][c];
        tr += X[c]*X[c];
        for (int i=c+1;i<NL;i++) {
            float s = 0.f;
            for (int j=c;j<i;j++) s += A[i][j]*X[j];
            X[i] = -s/A[i][i];
            tr += X[i]*X[i];
        }
    }
    float dz[NL];
    for (int k=NL-1;k>=0;k--) {
        float s = eps[b*NL+k];
        for (int j=k+1;j<NL;j++) s -= A[j][k]*dz[j];
        dz[k] = s/A[k][k];
    }
    float a0 = sb[0], a1 = sb[1];
    for (int n=0;n<NL;n++) {
        float zs = g_z1[b*NL+n] + dz[n];
        g_zs[b*NL+n] = zs;
        a0 = fmaf(zs, sW[n*2],   a0);
        a1 = fmaf(zs, sW[n*2+1], a1);
    }
    g_logdet[b] = ld;
    g_trinv[b] = tr;
    g_sp2[b] = expf(a0);
    g_sv2[b] = expf(a1);
}

__global__ __launch_bounds__(256) void delta_kernel(const float* __restrict__ x, const float* __restrict__ b2) {
    int b = blockIdx.y;
    int d = blockIdx.x*256 + threadIdx.x;
    float del = x[(size_t)b*DD+d] - (g_delta[(size_t)b*DD+d] + b2[d]);
    g_delta[(size_t)b*DD+d] = del;
    __shared__ float red[256];
    red[threadIdx.x] = del*del;
    __syncthreads();
    for (int s=128;s;s>>=1) { if (threadIdx.x<s) red[threadIdx.x]+=red[threadIdx.x+s]; __syncthreads(); }
    if (threadIdx.x==0) atomicAdd(&g_dsq[b], red[0]);
}

__global__ __launch_bounds__(256) void t_kernel(const float* __restrict__ W1) {
    int b = blockIdx.x, tid = threadIdx.x;
    int lane = tid & 31, s = tid >> 5;
    __shared__ float p[HH];
    for (int i=tid;i<HH;i+=256) p[i] = g_m2[b*HH+i]*g_v[b*HH+i];
    __syncthreads();
    #pragma unroll
    for (int nn=0; nn<4; nn++) {
        int n = s*4+nn;
        float acc = 0.f;
        for (int h=lane; h<HH; h+=32) acc = fmaf(p[h], W1[n*HH+h], acc);
        #pragma unroll
        for (int o=16;o;o>>=1) acc += __shfl_xor_sync(0xffffffffu, acc, o);
        if (lane==0) g_t[b*NL+n]=acc;
    }
}

__global__ void final_kernel(float* __restrict__ out) {
    int b = blockIdx.x*blockDim.x + threadIdx.x;
    if (b >= BB) return;
    float A[NL][NL];
    for (int i=0;i<NL;i++)
        for (int j=0;j<=i;j++) A[i][j] = g_G2[b*NL*NL + i*NL + j];
    chol32_serial(A);
    float y[NL];
    float dp = 0.f;
    for (int k=0;k<NL;k++) {
        float s = g_t[b*NL+k];
        for (int j=0;j<k;j++) s -= A[k][j]*y[j];
        y[k] = s/A[k][k];
        dp += y[k]*y[k];
    }
    float sp2 = g_sp2[b], sv2 = g_sv2[b];
    float recon = g_dsq[b]/(2.f*sv2*sv2)
                + dp*(0.5f/(sp2*sp2) - 0.5f/(sv2*sv2))
                + (float)NL*logf(sp2) + (float)(DD-NL)*logf(sv2);
    float latent = 0.5f*g_zn[b] + 0.5f*g_trinv[b];
    out[b] = (recon + latent + g_logdet[b]) / (float)DD;
}

extern "C" void kernel_launch(void* const* d_in, const int* in_sizes, int n_in,
                              void* d_out, int out_size) {
    const float* x      = (const float*)d_in[0];
    const float* eps    = (const float*)d_in[1];
    const float* enc_W1 = (const float*)d_in[2];
    const float* enc_b1 = (const float*)d_in[3];
    const float* enc_W2 = (const float*)d_in[4];
    const float* enc_b2 = (const float*)d_in[5];
    const float* dec_W1 = (const float*)d_in[6];
    const float* dec_b1 = (const float*)d_in[7];
    const float* dec_W2 = (const float*)d_in[8];
    const float* dec_b2 = (const float*)d_in[9];
    const float* sig_W  = (const float*)d_in[10];
    const float* sig_b  = (const float*)d_in[11];
    float* out = (float*)d_out;

    zero_kernel<<<256,256>>>();

    // C = dec_W2 @ dec_W2^T: upper tiles, split-K2 (272 blocks -> 2/SM), then mirror
    syrk_kernel<<<dim3(136,2),256>>>(dec_W2, DD/2);
    mirror_kernel<<<2080,1024>>>();

    // encoder: h1 = x @ enc_W1, split-K24 (384 blocks)
    gemm_k<64,128,16,4,8,false,true,0,0><<<dim3(16,1,24),256>>>(x, enc_W1, DD, HH, HH, 512);
    relu_bias_kernel<<<(BB*HH)/256,256>>>(enc_b1);
    z1_kernel<<<BB,256>>>(enc_W2, enc_b2);
    spsv_kernel<<<1,64>>>(sig_W, sig_b);
    sigterm_kernel<<<1,1024>>>(sig_W);

    // m1; T1 = (W1.*m1)@C; Prec
    dec_kernel<<<dim3(8,BB),256>>>(dec_W1, dec_b1, 0);
    t_gemm_kernel<<<dim3(16,BB),128>>>(dec_W1, 0);
    g_kernel<<<BB,1024>>>(dec_W1, 0);

    chol_prec_kernel<<<1,64>>>(eps, sig_W, sig_b);

    // decoder at z_s: m2,h2; x_star (split-K2 atomic into zeroed g_delta); delta,dsq
    dec_kernel<<<dim3(8,BB),256>>>(dec_W1, dec_b1, 1);
    gemm_k<64,128,16,4,8,false,true,1,1><<<dim3(96,1,2),256>>>(nullptr, dec_W2, HH, DD, DD, 1024);
    delta_kernel<<<dim3(48,BB),256>>>(x, dec_b2);

    // v = delta @ dec_W2^T, split-K24 (384 blocks)
    gemm_k<64,128,16,4,8,true,true,2,2><<<dim3(16,1,24),256>>>(nullptr, dec_W2, DD, DD, HH, 512);

    // T2, G2, t, final
    t_gemm_kernel<<<dim3(16,BB),128>>>(dec_W1, 1);
    g_kernel<<<BB,1024>>>(dec_W1, 1);
    t_kernel<<<BB,256>>>(dec_W1);
    final_kernel<<<1,64>>>(out);
}

// round 11
// speedup vs baseline: 1.3042x; 1.3042x over previous
#include <cuda_runtime.h>

#define BB 64
#define DD 12288
#define NL 32
#define HH 2048

__device__ float g_h1[BB*HH];
__device__ float g_z1[BB*NL];
__device__ float g_zn[BB];
__device__ float g_sp[BB];
__device__ float g_sp2[BB], g_sv2[BB];
__device__ float g_sigterm[NL*NL];
__device__ float g_C[HH*HH];
__device__ float g_m1[BB*HH];
__device__ float g_m2[BB*HH];
__device__ float g_h2[BB*HH];
__device__ float g_T[BB*NL*HH];
__device__ float g_P[BB*NL*NL];
__device__ float g_G2[BB*NL*NL];
__device__ float g_zs[BB*NL];
__device__ float g_logdet[BB], g_trinv[BB];
__device__ float g_delta[BB*DD];
__device__ float g_dsq[BB];
__device__ float g_v[BB*HH];
__device__ float g_t[BB*NL];

union F2U { float2 f; unsigned long long u; };
__device__ __forceinline__ float2 f2fma(float2 a, float2 b, float2 c) {
    F2U A, Bv, Cv, R; A.f = a; Bv.f = b; Cv.f = c;
    asm("fma.rn.f32x2 %0, %1, %2, %3;" : "=l"(R.u) : "l"(A.u), "l"(Bv.u), "l"(Cv.u));
    return R.f;
}

// device-side operand binding (NEVER pass __device__ symbols from host)
template<int SEL> __device__ __forceinline__ const float* bindA(const float* A) {
    if (SEL == 1) return g_h2;
    if (SEL == 2) return g_delta;
    return A;
}
template<int SEL> __device__ __forceinline__ float* bindC() {
    if (SEL == 0) return g_h1;
    if (SEL == 1) return g_delta;
    return g_v;
}

__global__ void zero_kernel() {
    int i = blockIdx.x*blockDim.x + threadIdx.x;
    int tot = gridDim.x*blockDim.x;
    for (int k=i;k<BB*HH;k+=tot) { g_h1[k]=0.f; g_v[k]=0.f; }
    if (i<BB) g_dsq[i]=0.f;
}

// C[m][n] (+)= sum_k A[m*lda+k] * (BT ? B[n*ldb+k] : B[k*ldb+n])
template<int BM,int BN,int BK,int TM,int TN,bool BT,bool ACC,int ASEL,int CSEL>
__global__ __launch_bounds__((BM/TM)*(BN/TN))
void gemm_k(const float* __restrict__ Ain, const float* __restrict__ B,
            int lda, int ldb, int ldc, int kChunk) {
    const float* __restrict__ A = bindA<ASEL>(Ain);
    float* __restrict__ C = bindC<CSEL>();
    constexpr int THREADS = (BM/TM)*(BN/TN);
    __shared__ float As[BK][BM+4];
    __shared__ float Bs[BK][BN+4];
    const int tid = threadIdx.x;
    const int tx = tid % (BN/TN), ty = tid / (BN/TN);
    const int row0 = blockIdx.y*BM, col0 = blockIdx.x*BN;
    const int k0 = blockIdx.z*kChunk, k1 = k0 + kChunk;
    float2 acc[TM][TN/2];
    #pragma unroll
    for (int i=0;i<TM;i++)
        #pragma unroll
        for (int j=0;j<TN/2;j++) acc[i][j]=make_float2(0.f,0.f);
    for (int kb=k0; kb<k1; kb+=BK) {
        for (int i=tid;i<BM*BK;i+=THREADS) {
            int m=i/BK, kk=i%BK;
            As[kk][m] = A[(size_t)(row0+m)*lda + kb+kk];
        }
        if (!BT) {
            for (int i=tid;i<BK*BN;i+=THREADS) {
                int kk=i/BN, n=i%BN;
                Bs[kk][n] = B[(size_t)(kb+kk)*ldb + col0+n];
            }
        } else {
            for (int i=tid;i<BK*BN;i+=THREADS) {
                int n=i/BK, kk=i%BK;
                Bs[kk][n] = B[(size_t)(col0+n)*ldb + kb+kk];
            }
        }
        __syncthreads();
        #pragma unroll
        for (int kk=0;kk<BK;kk++) {
            float a[TM]; float2 bb[TN/2];
            #pragma unroll
            for (int i=0;i<TM;i++) a[i]=As[kk][ty*TM+i];
            #pragma unroll
            for (int j=0;j<TN/2;j++) bb[j]=*(const float2*)&Bs[kk][tx*TN+2*j];
            #pragma unroll
            for (int i=0;i<TM;i++) {
                float2 a2 = make_float2(a[i],a[i]);
                #pragma unroll
                for (int j=0;j<TN/2;j++) acc[i][j]=f2fma(a2,bb[j],acc[i][j]);
            }
        }
        __syncthreads();
    }
    #pragma unroll
    for (int i=0;i<TM;i++) {
        int gm = row0+ty*TM+i;
        #pragma unroll
        for (int j=0;j<TN/2;j++) {
            int gn = col0+tx*TN+2*j;
            if (ACC) {
                atomicAdd(&C[(size_t)gm*ldc+gn],   acc[i][j].x);
                atomicAdd(&C[(size_t)gm*ldc+gn+1], acc[i][j].y);
            } else {
                *(float2*)&C[(size_t)gm*ldc+gn] = acc[i][j];
            }
        }
    }
}

__global__ void relu_bias_kernel(const float* __restrict__ b1) {
    int i = blockIdx.x*blockDim.x + threadIdx.x;
    if (i < BB*HH) g_h1[i] = fmaxf(g_h1[i] + b1[i & (HH-1)], 0.f);
}

__global__ __launch_bounds__(256) void z1_kernel(const float* __restrict__ W2e, const float* __restrict__ b2e) {
    int b = blockIdx.x, tid = threadIdx.x;
    __shared__ float hrow[HH];
    __shared__ float red[8][NL];
    for (int i=tid;i<HH;i+=256) hrow[i]=g_h1[b*HH+i];
    __syncthreads();
    int n = tid & 31, s = tid >> 5;
    float acc=0.f;
    for (int h=s;h<HH;h+=8) acc = fmaf(hrow[h], W2e[h*NL+n], acc);
    red[s][n]=acc;
    __syncthreads();
    if (tid < NL) {
        float z = b2e[tid];
        #pragma unroll
        for (int ss=0;ss<8;ss++) z += red[ss][tid];
        g_z1[b*NL+tid]=z;
    }
}

__global__ void spsv_kernel(const float* __restrict__ sW, const float* __restrict__ sb) {
    int b = threadIdx.x;
    if (b >= BB) return;
    float a0=sb[0], zn=0.f;
    #pragma unroll
    for (int n=0;n<NL;n++) {
        float z = g_z1[b*NL+n];
        a0 = fmaf(z, sW[n*2], a0);
        zn = fmaf(z, z, zn);
    }
    g_sp[b]=expf(a0); g_zn[b]=zn;
}

__global__ void sigterm_kernel(const float* __restrict__ sW) {
    int i = threadIdx.x;
    int n = i >> 5, m = i & 31;
    g_sigterm[i] = 0.5f*((float)NL*sW[n*2]*sW[m*2] + (float)(DD-NL)*sW[n*2+1]*sW[m*2+1]);
}

// C = W2 W2^T, upper 64x64 tiles (528 blocks -> 3-4/SM), direct stores
__global__ __launch_bounds__(256) void syrk64_kernel(const float* __restrict__ W2) {
    int p = blockIdx.x, ti = 0, cnt = 32;
    while (p >= cnt) { p -= cnt; cnt--; ti++; }
    int tj = ti + p;
    __shared__ float As[16][68];
    __shared__ float Bs[16][68];
    const int tid = threadIdx.x, tx = tid & 15, ty = tid >> 4;
    const float* Arow = W2 + (size_t)ti*64*DD;
    const float* Brow = W2 + (size_t)tj*64*DD;
    float2 acc[4][2];
    #pragma unroll
    for (int i=0;i<4;i++)
        #pragma unroll
        for (int j=0;j<2;j++) acc[i][j]=make_float2(0.f,0.f);
    for (int kb=0;kb<DD;kb+=16) {
        for (int i=tid;i<1024;i+=256) {
            int r=i>>4, c=i&15;
            As[c][r]=Arow[(size_t)r*DD+kb+c];
            Bs[c][r]=Brow[(size_t)r*DD+kb+c];
        }
        __syncthreads();
        #pragma unroll
        for (int kk=0;kk<16;kk++) {
            float4 a4=*(const float4*)&As[kk][ty*4];
            float4 b4=*(const float4*)&Bs[kk][tx*4];
            float av[4]={a4.x,a4.y,a4.z,a4.w};
            float2 bb[2]={{b4.x,b4.y},{b4.z,b4.w}};
            #pragma unroll
            for (int i=0;i<4;i++) {
                float2 a2 = make_float2(av[i],av[i]);
                #pragma unroll
                for (int j=0;j<2;j++) acc[i][j]=f2fma(a2,bb[j],acc[i][j]);
            }
        }
        __syncthreads();
    }
    #pragma unroll
    for (int i=0;i<4;i++) {
        int gi = ti*64 + ty*4 + i;
        #pragma unroll
        for (int j=0;j<2;j++) {
            int gj = tj*64 + tx*4 + 2*j;
            *(float2*)&g_C[(size_t)gi*HH + gj] = acc[i][j];
        }
    }
}

__global__ __launch_bounds__(1024) void mirror_kernel() {
    int p = blockIdx.x, ti = 0, cnt = 64;
    while (p >= cnt) { p -= cnt; cnt--; ti++; }
    int tj = ti + p;
    int tx = threadIdx.x & 31, ty = threadIdx.x >> 5;
    int i0 = ti*32, j0 = tj*32;
    if (ti == tj) {
        int i = i0+ty, j = j0+tx;
        if (j > i) g_C[(size_t)j*HH+i] = g_C[(size_t)i*HH+j];
    } else {
        __shared__ float tile[32][33];
        tile[ty][tx] = g_C[(size_t)(i0+ty)*HH + j0+tx];
        __syncthreads();
        g_C[(size_t)(j0+ty)*HH + i0+tx] = tile[tx][ty];
    }
}

__global__ __launch_bounds__(256) void dec_kernel(const float* __restrict__ W1, const float* __restrict__ b1, int useZs) {
    int b = blockIdx.y;
    int h = blockIdx.x*256 + threadIdx.x;
    __shared__ float zs[NL];
    if (threadIdx.x < NL) zs[threadIdx.x] = useZs ? g_zs[b*NL+threadIdx.x] : g_z1[b*NL+threadIdx.x];
    __syncthreads();
    float acc = b1[h];
    #pragma unroll
    for (int n=0;n<NL;n++) acc = fmaf(zs[n], W1[n*HH+h], acc);
    if (useZs) {
        g_m2[b*HH+h] = acc>0.f?1.f:0.f;
        g_h2[b*HH+h] = fmaxf(acc, 0.f);
    } else {
        g_m1[b*HH+h] = acc>0.f?1.f:0.f;
    }
}

__global__ __launch_bounds__(128) void t_gemm_kernel(const float* __restrict__ W1, int useM2) {
    int b = blockIdx.y;
    int col0 = blockIdx.x*128;
    const float* mrow = (useM2 ? g_m2 : g_m1) + b*HH;
    __shared__ float As[32][33];
    __shared__ float Bs[32][132];
    const int tid = threadIdx.x, tx = tid & 15, ty = tid >> 4;
    float2 acc[4][4];
    #pragma unroll
    for (int i=0;i<4;i++)
        #pragma unroll
        for (int j=0;j<4;j++) acc[i][j]=make_float2(0.f,0.f);
    for (int kb=0;kb<HH;kb+=32) {
        for (int i=tid;i<1024;i+=128) { int n=i>>5, kk=i&31; As[kk][n]=W1[n*HH+kb+kk]*mrow[kb+kk]; }
        for (int i=tid;i<4096;i+=128) { int kk=i>>7, n=i&127; Bs[kk][n]=g_C[(size_t)(kb+kk)*HH + col0+n]; }
        __syncthreads();
        #pragma unroll
        for (int kk=0;kk<32;kk++) {
            float a[4];
            #pragma unroll
            for (int i=0;i<4;i++) a[i]=As[kk][ty*4+i];
            float4 b0=*(const float4*)&Bs[kk][tx*8], b1=*(const float4*)&Bs[kk][tx*8+4];
            float2 bb[4]={{b0.x,b0.y},{b0.z,b0.w},{b1.x,b1.y},{b1.z,b1.w}};
            #pragma unroll
            for (int i=0;i<4;i++) {
                float2 a2=make_float2(a[i],a[i]);
                #pragma unroll
                for (int j=0;j<4;j++) acc[i][j]=f2fma(a2,bb[j],acc[i][j]);
            }
        }
        __syncthreads();
    }
    #pragma unroll
    for (int i=0;i<4;i++) {
        int n = ty*4+i;
        #pragma unroll
        for (int j=0;j<4;j++) {
            int c = col0 + tx*8 + 2*j;
            *(float2*)&g_T[(size_t)b*NL*HH + n*HH + c] = acc[i][j];
        }
    }
}

__global__ __launch_bounds__(1024) void g_kernel(const float* __restrict__ W1, int mode) {
    int b = blockIdx.x;
    int tx = threadIdx.x & 31, ty = threadIdx.x >> 5;
    const float* mrow = (mode ? g_m2 : g_m1) + b*HH;
    __shared__ float Ts[32][33], Ws[32][33];
    float acc = 0.f;
    for (int j0=0;j0<HH;j0+=32) {
        Ts[ty][tx] = g_T[(size_t)b*NL*HH + ty*HH + j0+tx];
        Ws[ty][tx] = W1[ty*HH + j0+tx]*mrow[j0+tx];
        __syncthreads();
        #pragma unroll
        for (int jj=0;jj<32;jj++) acc = fmaf(Ts[ty][jj], Ws[tx][jj], acc);
        __syncthreads();
    }
    if (mode == 0) {
        float sp = g_sp[b];
        float val = acc/(sp*sp) + g_sigterm[ty*NL+tx] + (tx==ty ? 1.f : 0.f);
        g_P[b*NL*NL + ty*NL + tx] = val;
    } else {
        g_G2[b*NL*NL + ty*NL + tx] = acc;
    }
}

__device__ void chol32_serial(float A[NL][NL]) {
    for (int k=0;k<NL;k++) {
        A[k][k] = sqrtf(A[k][k]);
        float inv = 1.f/A[k][k];
        for (int i=k+1;i<NL;i++) A[i][k] *= inv;
        for (int i=k+1;i<NL;i++) {
            float lik = A[i][k];
            for (int j=k+1;j<=i;j++) A[i][j] -= lik*A[j][k];
        }
    }
}

__global__ void chol_prec_kernel(const float* __restrict__ eps, const float* __restrict__ sW, const float* __restrict__ sb) {
    int b = blockIdx.x*blockDim.x + threadIdx.x;
    if (b >= BB) return;
    float A[NL][NL];
    for (int i=0;i<NL;i++)
        for (int j=0;j<=i;j++) A[i][j] = g_P[b*NL*NL + i*NL + j];
    chol32_serial(A);
    float ld = 0.f;
    for (int k=0;k<NL;k++) ld += logf(A[k][k]);
    float tr = 0.f;
    float X[NL];
    for (int c=0;c<NL;c++) {
        X[c] = 1.f/A[c][c];
        tr += X[c]*X[c];
        for (int i=c+1;i<NL;i++) {
            float s = 0.f;
            for (int j=c;j<i;j++) s += A[i][j]*X[j];
            X[i] = -s/A[i][i];
            tr += X[i]*X[i];
        }
    }
    float dz[NL];
    for (int k=NL-1;k>=0;k--) {
        float s = eps[b*NL+k];
        for (int j=k+1;j<NL;j++) s -= A[j][k]*dz[j];
        dz[k] = s/A[k][k];
    }
    float a0 = sb[0], a1 = sb[1];
    for (int n=0;n<NL;n++) {
        float zs = g_z1[b*NL+n] + dz[n];
        g_zs[b*NL+n] = zs;
        a0 = fmaf(zs, sW[n*2],   a0);
        a1 = fmaf(zs, sW[n*2+1], a1);
    }
    g_logdet[b] = ld;
    g_trinv[b] = tr;
    g_sp2[b] = expf(a0);
    g_sv2[b] = expf(a1);
}

__global__ __launch_bounds__(256) void delta_kernel(const float* __restrict__ x, const float* __restrict__ b2) {
    int b = blockIdx.y;
    int d = blockIdx.x*256 + threadIdx.x;
    float del = x[(size_t)b*DD+d] - (g_delta[(size_t)b*DD+d] + b2[d]);
    g_delta[(size_t)b*DD+d] = del;
    __shared__ float red[256];
    red[threadIdx.x] = del*del;
    __syncthreads();
    for (int s=128;s;s>>=1) { if (threadIdx.x<s) red[threadIdx.x]+=red[threadIdx.x+s]; __syncthreads(); }
    if (threadIdx.x==0) atomicAdd(&g_dsq[b], red[0]);
}

__global__ __launch_bounds__(256) void t_kernel(const float* __restrict__ W1) {
    int b = blockIdx.x, tid = threadIdx.x;
    int lane = tid & 31, s = tid >> 5;
    __shared__ float p[HH];
    for (int i=tid;i<HH;i+=256) p[i] = g_m2[b*HH+i]*g_v[b*HH+i];
    __syncthreads();
    #pragma unroll
    for (int nn=0; nn<4; nn++) {
        int n = s*4+nn;
        float acc = 0.f;
        for (int h=lane; h<HH; h+=32) acc = fmaf(p[h], W1[n*HH+h], acc);
        #pragma unroll
        for (int o=16;o;o>>=1) acc += __shfl_xor_sync(0xffffffffu, acc, o);
        if (lane==0) g_t[b*NL+n]=acc;
    }
}

__global__ void final_kernel(float* __restrict__ out) {
    int b = blockIdx.x*blockDim.x + threadIdx.x;
    if (b >= BB) return;
    float A[NL][NL];
    for (int i=0;i<NL;i++)
        for (int j=0;j<=i;j++) A[i][j] = g_G2[b*NL*NL + i*NL + j];
    chol32_serial(A);
    float y[NL];
    float dp = 0.f;
    for (int k=0;k<NL;k++) {
        float s = g_t[b*NL+k];
        for (int j=0;j<k;j++) s -= A[k][j]*y[j];
        y[k] = s/A[k][k];
        dp += y[k]*y[k];
    }
    float sp2 = g_sp2[b], sv2 = g_sv2[b];
    float recon = g_dsq[b]/(2.f*sv2*sv2)
                + dp*(0.5f/(sp2*sp2) - 0.5f/(sv2*sv2))
                + (float)NL*logf(sp2) + (float)(DD-NL)*logf(sv2);
    float latent = 0.5f*g_zn[b] + 0.5f*g_trinv[b];
    out[b] = (recon + latent + g_logdet[b]) / (float)DD;
}

extern "C" void kernel_launch(void* const* d_in, const int* in_sizes, int n_in,
                              void* d_out, int out_size) {
    const float* x      = (const float*)d_in[0];
    const float* eps    = (const float*)d_in[1];
    const float* enc_W1 = (const float*)d_in[2];
    const float* enc_b1 = (const float*)d_in[3];
    const float* enc_W2 = (const float*)d_in[4];
    const float* enc_b2 = (const float*)d_in[5];
    const float* dec_W1 = (const float*)d_in[6];
    const float* dec_b1 = (const float*)d_in[7];
    const float* dec_W2 = (const float*)d_in[8];
    const float* dec_b2 = (const float*)d_in[9];
    const float* sig_W  = (const float*)d_in[10];
    const float* sig_b  = (const float*)d_in[11];
    float* out = (float*)d_out;

    zero_kernel<<<256,256>>>();

    // C = dec_W2 @ dec_W2^T: 64x64 upper tiles (528 blocks), then mirror
    syrk64_kernel<<<528,256>>>(dec_W2);
    mirror_kernel<<<2080,1024>>>();

    // encoder: h1 = x @ enc_W1, split-K24 (384 blocks, atomic into zeroed g_h1)
    gemm_k<64,128,16,4,8,false,true,0,0><<<dim3(16,1,24),256>>>(x, enc_W1, DD, HH, HH, 512);
    relu_bias_kernel<<<(BB*HH)/256,256>>>(enc_b1);
    z1_kernel<<<BB,256>>>(enc_W2, enc_b2);
    spsv_kernel<<<1,64>>>(sig_W, sig_b);
    sigterm_kernel<<<1,1024>>>(sig_W);

    // m1; T1 = (W1.*m1)@C; Prec
    dec_kernel<<<dim3(8,BB),256>>>(dec_W1, dec_b1, 0);
    t_gemm_kernel<<<dim3(16,BB),128>>>(dec_W1, 0);
    g_kernel<<<BB,1024>>>(dec_W1, 0);

    chol_prec_kernel<<<1,64>>>(eps, sig_W, sig_b);

    // decoder at z_s: m2,h2; x_star (direct store); delta,dsq
    dec_kernel<<<dim3(8,BB),256>>>(dec_W1, dec_b1, 1);
    gemm_k<64,128,16,4,8,false,false,1,1><<<dim3(96,1,1),256>>>(nullptr, dec_W2, HH, DD, DD, 2048);
    delta_kernel<<<dim3(48,BB),256>>>(x, dec_b2);

    // v = delta @ dec_W2^T, split-K24 (384 blocks, atomic into zeroed g_v)
    gemm_k<64,128,16,4,8,true,true,2,2><<<dim3(16,1,24),256>>>(nullptr, dec_W2, DD, DD, HH, 512);

    // T2, G2, t, final
    t_gemm_kernel<<<dim3(16,BB),128>>>(dec_W1, 1);
    g_kernel<<<BB,1024>>>(dec_W1, 1);
    t_kernel<<<BB,256>>>(dec_W1);
    final_kernel<<<1,64>>>(out);
}

// round 14
// speedup vs baseline: 1.8593x; 1.4256x over previous
#include <cuda_runtime.h>
#include <cuda_bf16.h>
#include <cstdint>

#define BB 64
#define DD 12288
#define NL 32
#define HH 2048

__device__ float g_h1[BB*HH];
__device__ float g_z1[BB*NL];
__device__ float g_zn[BB];
__device__ float g_sp[BB];
__device__ float g_sp2[BB], g_sv2[BB];
__device__ float g_sigterm[NL*NL];
__device__ float g_C[HH*HH];
__device__ float g_m1[BB*HH];
__device__ float g_m2[BB*HH];
__device__ float g_h2[BB*HH];
__device__ float g_T[BB*NL*HH];
__device__ float g_P[BB*NL*NL];
__device__ float g_G2[BB*NL*NL];
__device__ float g_zs[BB*NL];
__device__ float g_logdet[BB], g_trinv[BB];
__device__ float g_delta[BB*DD];
__device__ float g_dsq[BB];
__device__ float g_v[BB*HH];
__device__ float g_t[BB*NL];
__device__ __nv_bfloat16 g_w2bf[(size_t)HH*DD];   // bf16 copy of dec_W2 (50MB)

union F2U { float2 f; unsigned long long u; };
__device__ __forceinline__ float2 f2fma(float2 a, float2 b, float2 c) {
    F2U A, Bv, Cv, R; A.f = a; Bv.f = b; Cv.f = c;
    asm("fma.rn.f32x2 %0, %1, %2, %3;" : "=l"(R.u) : "l"(A.u), "l"(Bv.u), "l"(Cv.u));
    return R.f;
}

__device__ __forceinline__ void mma16816(float* c, const uint32_t* a, const uint32_t* b) {
    asm volatile(
        "mma.sync.aligned.m16n8k16.row.col.f32.bf16.bf16.f32 "
        "{%0,%1,%2,%3}, {%4,%5,%6,%7}, {%8,%9}, {%0,%1,%2,%3};"
        : "+f"(c[0]), "+f"(c[1]), "+f"(c[2]), "+f"(c[3])
        : "r"(a[0]), "r"(a[1]), "r"(a[2]), "r"(a[3]), "r"(b[0]), "r"(b[1]));
}

// device-side operand binding (NEVER pass __device__ symbols from host)
template<int SEL> __device__ __forceinline__ const float* bindA(const float* A) {
    if (SEL == 1) return g_h2;
    if (SEL == 2) return g_delta;
    return A;
}
template<int SEL> __device__ __forceinline__ float* bindC() {
    if (SEL == 0) return g_h1;
    if (SEL == 1) return g_delta;
    return g_v;
}

__global__ void zero_kernel() {
    int i = blockIdx.x*blockDim.x + threadIdx.x;
    int tot = gridDim.x*blockDim.x;
    for (int k=i;k<BB*HH;k+=tot) { g_h1[k]=0.f; g_v[k]=0.f; }
    if (i<BB) g_dsq[i]=0.f;
}

// fp32 -> bf16 convert of dec_W2
__global__ __launch_bounds__(256) void w2bf_kernel(const float* __restrict__ W2) {
    size_t i = (size_t)blockIdx.x*256 + threadIdx.x;   // float4 index
    float4 v = ((const float4*)W2)[i];
    __nv_bfloat162 lo, hi;
    lo.x = __float2bfloat16(v.x); lo.y = __float2bfloat16(v.y);
    hi.x = __float2bfloat16(v.z); hi.y = __float2bfloat16(v.w);
    ((__nv_bfloat162*)g_w2bf)[2*i]   = lo;
    ((__nv_bfloat162*)g_w2bf)[2*i+1] = hi;
}

// C = W2 W2^T upper 128x128 tiles via mma.sync bf16 (HMMA), fp32 accum.
// 8 warps: warp tile 64x32 (wm=wid>>2 in {0,1}, wn=wid&3 in {0..3}).
// smem row stride 40 halves -> fragment LDS is 32-bank conflict-free.
__global__ __launch_bounds__(256) void syrk_mma_kernel() {
    __shared__ __nv_bfloat16 As[128*40];
    __shared__ __nv_bfloat16 Bs[128*40];
    const int tid = threadIdx.x, wid = tid>>5, lane = tid&31;
    const int gid = lane>>2, tig = lane&3;
    int p = blockIdx.x, ti = 0, cnt = 16;
    while (p >= cnt) { p -= cnt; cnt--; ti++; }
    const int tj = ti + p;
    const int wm = wid>>2, wn = wid&3;
    const __nv_bfloat16* Arows = g_w2bf + (size_t)ti*128*DD;
    const __nv_bfloat16* Brows = g_w2bf + (size_t)tj*128*DD;

    float acc[4][4][4];
    #pragma unroll
    for (int i=0;i<4;i++)
        #pragma unroll
        for (int j=0;j<4;j++)
            #pragma unroll
            for (int q=0;q<4;q++) acc[i][j][q]=0.f;

    for (int kb=0; kb<DD; kb+=32) {
        #pragma unroll
        for (int t=0;t<2;t++) {
            int u = tid + t*256;
            int row = u>>2, q = u&3;
            *(uint4*)&As[row*40+q*8] = *(const uint4*)(Arows + (size_t)row*DD + kb + q*8);
            *(uint4*)&Bs[row*40+q*8] = *(const uint4*)(Brows + (size_t)row*DD + kb + q*8);
        }
        __syncthreads();
        #pragma unroll
        for (int ks=0; ks<2; ks++) {
            const int k0 = ks*16;
            uint32_t afr[4][4], bfr[4][2];
            #pragma unroll
            for (int i=0;i<4;i++) {
                int r = wm*64 + i*16 + gid;
                afr[i][0] = *(const uint32_t*)&As[r*40     + k0 + 2*tig];
                afr[i][1] = *(const uint32_t*)&As[(r+8)*40 + k0 + 2*tig];
                afr[i][2] = *(const uint32_t*)&As[r*40     + k0 + 8 + 2*tig];
                afr[i][3] = *(const uint32_t*)&As[(r+8)*40 + k0 + 8 + 2*tig];
            }
            #pragma unroll
            for (int j=0;j<4;j++) {
                int c = wn*32 + j*8 + gid;
                bfr[j][0] = *(const uint32_t*)&Bs[c*40 + k0 + 2*tig];
                bfr[j][1] = *(const uint32_t*)&Bs[c*40 + k0 + 8 + 2*tig];
            }
            #pragma unroll
            for (int i=0;i<4;i++)
                #pragma unroll
                for (int j=0;j<4;j++)
                    mma16816(acc[i][j], afr[i], bfr[j]);
        }
        __syncthreads();
    }
    #pragma unroll
    for (int i=0;i<4;i++) {
        int r = ti*128 + wm*64 + i*16 + gid;
        #pragma unroll
        for (int j=0;j<4;j++) {
            int c = tj*128 + wn*32 + j*8 + 2*tig;
            *(float2*)&g_C[(size_t)r*HH + c]     = make_float2(acc[i][j][0], acc[i][j][1]);
            *(float2*)&g_C[(size_t)(r+8)*HH + c] = make_float2(acc[i][j][2], acc[i][j][3]);
        }
    }
}

// C[m][n] (+)= sum_k A[m*lda+k] * (BT ? B[n*ldb+k] : B[k*ldb+n])
template<int BM,int BN,int BK,int TM,int TN,bool BT,bool ACC,int ASEL,int CSEL>
__global__ __launch_bounds__((BM/TM)*(BN/TN))
void gemm_k(const float* __restrict__ Ain, const float* __restrict__ B,
            int lda, int ldb, int ldc, int kChunk) {
    const float* __restrict__ A = bindA<ASEL>(Ain);
    float* __restrict__ C = bindC<CSEL>();
    constexpr int THREADS = (BM/TM)*(BN/TN);
    __shared__ float As[BK][BM+4];
    __shared__ float Bs[BK][BN+4];
    const int tid = threadIdx.x;
    const int tx = tid % (BN/TN), ty = tid / (BN/TN);
    const int row0 = blockIdx.y*BM, col0 = blockIdx.x*BN;
    const int k0 = blockIdx.z*kChunk, k1 = k0 + kChunk;
    float2 acc[TM][TN/2];
    #pragma unroll
    for (int i=0;i<TM;i++)
        #pragma unroll
        for (int j=0;j<TN/2;j++) acc[i][j]=make_float2(0.f,0.f);
    for (int kb=k0; kb<k1; kb+=BK) {
        for (int i=tid;i<BM*BK;i+=THREADS) {
            int m=i/BK, kk=i%BK;
            As[kk][m] = A[(size_t)(row0+m)*lda + kb+kk];
        }
        if (!BT) {
            for (int i=tid;i<BK*BN;i+=THREADS) {
                int kk=i/BN, n=i%BN;
                Bs[kk][n] = B[(size_t)(kb+kk)*ldb + col0+n];
            }
        } else {
            for (int i=tid;i<BK*BN;i+=THREADS) {
                int n=i/BK, kk=i%BK;
                Bs[kk][n] = B[(size_t)(col0+n)*ldb + kb+kk];
            }
        }
        __syncthreads();
        #pragma unroll
        for (int kk=0;kk<BK;kk++) {
            float a[TM]; float2 bb[TN/2];
            #pragma unroll
            for (int i=0;i<TM;i++) a[i]=As[kk][ty*TM+i];
            #pragma unroll
            for (int j=0;j<TN/2;j++) bb[j]=*(const float2*)&Bs[kk][tx*TN+2*j];
            #pragma unroll
            for (int i=0;i<TM;i++) {
                float2 a2 = make_float2(a[i],a[i]);
                #pragma unroll
                for (int j=0;j<TN/2;j++) acc[i][j]=f2fma(a2,bb[j],acc[i][j]);
            }
        }
        __syncthreads();
    }
    #pragma unroll
    for (int i=0;i<TM;i++) {
        int gm = row0+ty*TM+i;
        #pragma unroll
        for (int j=0;j<TN/2;j++) {
            int gn = col0+tx*TN+2*j;
            if (ACC) {
                atomicAdd(&C[(size_t)gm*ldc+gn],   acc[i][j].x);
                atomicAdd(&C[(size_t)gm*ldc+gn+1], acc[i][j].y);
            } else {
                *(float2*)&C[(size_t)gm*ldc+gn] = acc[i][j];
            }
        }
    }
}

__global__ void relu_bias_kernel(const float* __restrict__ b1) {
    int i = blockIdx.x*blockDim.x + threadIdx.x;
    if (i < BB*HH) g_h1[i] = fmaxf(g_h1[i] + b1[i & (HH-1)], 0.f);
}

__global__ __launch_bounds__(256) void z1_kernel(const float* __restrict__ W2e, const float* __restrict__ b2e) {
    int b = blockIdx.x, tid = threadIdx.x;
    __shared__ float hrow[HH];
    __shared__ float red[8][NL];
    for (int i=tid;i<HH;i+=256) hrow[i]=g_h1[b*HH+i];
    __syncthreads();
    int n = tid & 31, s = tid >> 5;
    float acc=0.f;
    for (int h=s;h<HH;h+=8) acc = fmaf(hrow[h], W2e[h*NL+n], acc);
    red[s][n]=acc;
    __syncthreads();
    if (tid < NL) {
        float z = b2e[tid];
        #pragma unroll
        for (int ss=0;ss<8;ss++) z += red[ss][tid];
        g_z1[b*NL+tid]=z;
    }
}

__global__ void spsv_kernel(const float* __restrict__ sW, const float* __restrict__ sb) {
    int b = threadIdx.x;
    if (b >= BB) return;
    float a0=sb[0], zn=0.f;
    #pragma unroll
    for (int n=0;n<NL;n++) {
        float z = g_z1[b*NL+n];
        a0 = fmaf(z, sW[n*2], a0);
        zn = fmaf(z, z, zn);
    }
    g_sp[b]=expf(a0); g_zn[b]=zn;
}

__global__ void sigterm_kernel(const float* __restrict__ sW) {
    int i = threadIdx.x;
    int n = i >> 5, m = i & 31;
    g_sigterm[i] = 0.5f*((float)NL*sW[n*2]*sW[m*2] + (float)(DD-NL)*sW[n*2+1]*sW[m*2+1]);
}

__global__ __launch_bounds__(1024) void mirror_kernel() {
    int p = blockIdx.x, ti = 0, cnt = 64;
    while (p >= cnt) { p -= cnt; cnt--; ti++; }
    int tj = ti + p;
    int tx = threadIdx.x & 31, ty = threadIdx.x >> 5;
    int i0 = ti*32, j0 = tj*32;
    if (ti == tj) {
        int i = i0+ty, j = j0+tx;
        if (j > i) g_C[(size_t)j*HH+i] = g_C[(size_t)i*HH+j];
    } else {
        __shared__ float tile[32][33];
        tile[ty][tx] = g_C[(size_t)(i0+ty)*HH + j0+tx];
        __syncthreads();
        g_C[(size_t)(j0+ty)*HH + i0+tx] = tile[tx][ty];
    }
}

__global__ __launch_bounds__(256) void dec_kernel(const float* __restrict__ W1, const float* __restrict__ b1, int useZs) {
    int b = blockIdx.y;
    int h = blockIdx.x*256 + threadIdx.x;
    __shared__ float zs[NL];
    if (threadIdx.x < NL) zs[threadIdx.x] = useZs ? g_zs[b*NL+threadIdx.x] : g_z1[b*NL+threadIdx.x];
    __syncthreads();
    float acc = b1[h];
    #pragma unroll
    for (int n=0;n<NL;n++) acc = fmaf(zs[n], W1[n*HH+h], acc);
    if (useZs) {
        g_m2[b*HH+h] = acc>0.f?1.f:0.f;
        g_h2[b*HH+h] = fmaxf(acc, 0.f);
    } else {
        g_m1[b*HH+h] = acc>0.f?1.f:0.f;
    }
}

__global__ __launch_bounds__(128) void t_gemm_kernel(const float* __restrict__ W1, int useM2) {
    int b = blockIdx.y;
    int col0 = blockIdx.x*128;
    const float* mrow = (useM2 ? g_m2 : g_m1) + b*HH;
    __shared__ float As[32][33];
    __shared__ float Bs[32][132];
    const int tid = threadIdx.x, tx = tid & 15, ty = tid >> 4;
    float2 acc[4][4];
    #pragma unroll
    for (int i=0;i<4;i++)
        #pragma unroll
        for (int j=0;j<4;j++) acc[i][j]=make_float2(0.f,0.f);
    for (int kb=0;kb<HH;kb+=32) {
        for (int i=tid;i<1024;i+=128) { int n=i>>5, kk=i&31; As[kk][n]=W1[n*HH+kb+kk]*mrow[kb+kk]; }
        for (int i=tid;i<4096;i+=128) { int kk=i>>7, n=i&127; Bs[kk][n]=g_C[(size_t)(kb+kk)*HH + col0+n]; }
        __syncthreads();
        #pragma unroll
        for (int kk=0;kk<32;kk++) {
            float a[4];
            #pragma unroll
            for (int i=0;i<4;i++) a[i]=As[kk][ty*4+i];
            float4 b0=*(const float4*)&Bs[kk][tx*8], b1=*(const float4*)&Bs[kk][tx*8+4];
            float2 bb[4]={{b0.x,b0.y},{b0.z,b0.w},{b1.x,b1.y},{b1.z,b1.w}};
            #pragma unroll
            for (int i=0;i<4;i++) {
                float2 a2=make_float2(a[i],a[i]);
                #pragma unroll
                for (int j=0;j<4;j++) acc[i][j]=f2fma(a2,bb[j],acc[i][j]);
            }
        }
        __syncthreads();
    }
    #pragma unroll
    for (int i=0;i<4;i++) {
        int n = ty*4+i;
        #pragma unroll
        for (int j=0;j<4;j++) {
            int c = col0 + tx*8 + 2*j;
            *(float2*)&g_T[(size_t)b*NL*HH + n*HH + c] = acc[i][j];
        }
    }
}

__global__ __launch_bounds__(1024) void g_kernel(const float* __restrict__ W1, int mode) {
    int b = blockIdx.x;
    int tx = threadIdx.x & 31, ty = threadIdx.x >> 5;
    const float* mrow = (mode ? g_m2 : g_m1) + b*HH;
    __shared__ float Ts[32][33], Ws[32][33];
    float acc = 0.f;
    for (int j0=0;j0<HH;j0+=32) {
        Ts[ty][tx] = g_T[(size_t)b*NL*HH + ty*HH + j0+tx];
        Ws[ty][tx] = W1[ty*HH + j0+tx]*mrow[j0+tx];
        __syncthreads();
        #pragma unroll
        for (int jj=0;jj<32;jj++) acc = fmaf(Ts[ty][jj], Ws[tx][jj], acc);
        __syncthreads();
    }
    if (mode == 0) {
        float sp = g_sp[b];
        float val = acc/(sp*sp) + g_sigterm[ty*NL+tx] + (tx==ty ? 1.f : 0.f);
        g_P[b*NL*NL + ty*NL + tx] = val;
    } else {
        g_G2[b*NL*NL + ty*NL + tx] = acc;
    }
}

__device__ void chol32_serial(float A[NL][NL]) {
    for (int k=0;k<NL;k++) {
        A[k][k] = sqrtf(A[k][k]);
        float inv = 1.f/A[k][k];
        for (int i=k+1;i<NL;i++) A[i][k] *= inv;
        for (int i=k+1;i<NL;i++) {
            float lik = A[i][k];
            for (int j=k+1;j<=i;j++) A[i][j] -= lik*A[j][k];
        }
    }
}

__global__ void chol_prec_kernel(const float* __restrict__ eps, const float* __restrict__ sW, const float* __restrict__ sb) {
    int b = blockIdx.x*blockDim.x + threadIdx.x;
    if (b >= BB) return;
    float A[NL][NL];
    for (int i=0;i<NL;i++)
        for (int j=0;j<=i;j++) A[i][j] = g_P[b*NL*NL + i*NL + j];
    chol32_serial(A);
    float ld = 0.f;
    for (int k=0;k<NL;k++) ld += logf(A[k][k]);
    float tr = 0.f;
    float X[NL];
    for (int c=0;c<NL;c++) {
        X[c] = 1.f/A[c][c];
        tr += X[c]*X[c];
        for (int i=c+1;i<NL;i++) {
            float s = 0.f;
            for (int j=c;j<i;j++) s += A[i][j]*X[j];
            X[i] = -s/A[i][i];
            tr += X[i]*X[i];
        }
    }
    float dz[NL];
    for (int k=NL-1;k>=0;k--) {
        float s = eps[b*NL+k];
        for (int j=k+1;j<NL;j++) s -= A[j][k]*dz[j];
        dz[k] = s/A[k][k];
    }
    float a0 = sb[0], a1 = sb[1];
    for (int n=0;n<NL;n++) {
        float zs = g_z1[b*NL+n] + dz[n];
        g_zs[b*NL+n] = zs;
        a0 = fmaf(zs, sW[n*2],   a0);
        a1 = fmaf(zs, sW[n*2+1], a1);
    }
    g_logdet[b] = ld;
    g_trinv[b] = tr;
    g_sp2[b] = expf(a0);
    g_sv2[b] = expf(a1);
}

__global__ __launch_bounds__(256) void delta_kernel(const float* __restrict__ x, const float* __restrict__ b2) {
    int b = blockIdx.y;
    int d = blockIdx.x*256 + threadIdx.x;
    float del = x[(size_t)b*DD+d] - (g_delta[(size_t)b*DD+d] + b2[d]);
    g_delta[(size_t)b*DD+d] = del;
    __shared__ float red[256];
    red[threadIdx.x] = del*del;
    __syncthreads();
    for (int s=128;s;s>>=1) { if (threadIdx.x<s) red[threadIdx.x]+=red[threadIdx.x+s]; __syncthreads(); }
    if (threadIdx.x==0) atomicAdd(&g_dsq[b], red[0]);
}

__global__ __launch_bounds__(256) void t_kernel(const float* __restrict__ W1) {
    int b = blockIdx.x, tid = threadIdx.x;
    int lane = tid & 31, s = tid >> 5;
    __shared__ float p[HH];
    for (int i=tid;i<HH;i+=256) p[i] = g_m2[b*HH+i]*g_v[b*HH+i];
    __syncthreads();
    #pragma unroll
    for (int nn=0; nn<4; nn++) {
        int n = s*4+nn;
        float acc = 0.f;
        for (int h=lane; h<HH; h+=32) acc = fmaf(p[h], W1[n*HH+h], acc);
        #pragma unroll
        for (int o=16;o;o>>=1) acc += __shfl_xor_sync(0xffffffffu, acc, o);
        if (lane==0) g_t[b*NL+n]=acc;
    }
}

__global__ void final_kernel(float* __restrict__ out) {
    int b = blockIdx.x*blockDim.x + threadIdx.x;
    if (b >= BB) return;
    float A[NL][NL];
    for (int i=0;i<NL;i++)
        for (int j=0;j<=i;j++) A[i][j] = g_G2[b*NL*NL + i*NL + j];
    chol32_serial(A);
    float y[NL];
    float dp = 0.f;
    for (int k=0;k<NL;k++) {
        float s = g_t[b*NL+k];
        for (int j=0;j<k;j++) s -= A[k][j]*y[j];
        y[k] = s/A[k][k];
        dp += y[k]*y[k];
    }
    float sp2 = g_sp2[b], sv2 = g_sv2[b];
    float recon = g_dsq[b]/(2.f*sv2*sv2)
                + dp*(0.5f/(sp2*sp2) - 0.5f/(sv2*sv2))
                + (float)NL*logf(sp2) + (float)(DD-NL)*logf(sv2);
    float latent = 0.5f*g_zn[b] + 0.5f*g_trinv[b];
    out[b] = (recon + latent + g_logdet[b]) / (float)DD;
}

extern "C" void kernel_launch(void* const* d_in, const int* in_sizes, int n_in,
                              void* d_out, int out_size) {
    const float* x      = (const float*)d_in[0];
    const float* eps    = (const float*)d_in[1];
    const float* enc_W1 = (const float*)d_in[2];
    const float* enc_b1 = (const float*)d_in[3];
    const float* enc_W2 = (const float*)d_in[4];
    const float* enc_b2 = (const float*)d_in[5];
    const float* dec_W1 = (const float*)d_in[6];
    const float* dec_b1 = (const float*)d_in[7];
    const float* dec_W2 = (const float*)d_in[8];
    const float* dec_b2 = (const float*)d_in[9];
    const float* sig_W  = (const float*)d_in[10];
    const float* sig_b  = (const float*)d_in[11];
    float* out = (float*)d_out;

    zero_kernel<<<256,256>>>();

    // bf16 copy of dec_W2, then HMMA syrk (upper tiles) + mirror
    w2bf_kernel<<<(HH*DD/4)/256,256>>>(dec_W2);
    syrk_mma_kernel<<<136,256>>>();
    mirror_kernel<<<2080,1024>>>();

    // encoder: h1 = x @ enc_W1, split-K24 (atomic into zeroed g_h1)
    gemm_k<64,128,16,4,8,false,true,0,0><<<dim3(16,1,24),256>>>(x, enc_W1, DD, HH, HH, 512);
    relu_bias_kernel<<<(BB*HH)/256,256>>>(enc_b1);
    z1_kernel<<<BB,256>>>(enc_W2, enc_b2);
    spsv_kernel<<<1,64>>>(sig_W, sig_b);
    sigterm_kernel<<<1,1024>>>(sig_W);

    // m1; T1 = (W1.*m1)@C; Prec
    dec_kernel<<<dim3(8,BB),256>>>(dec_W1, dec_b1, 0);
    t_gemm_kernel<<<dim3(16,BB),128>>>(dec_W1, 0);
    g_kernel<<<BB,1024>>>(dec_W1, 0);

    chol_prec_kernel<<<1,64>>>(eps, sig_W, sig_b);

    // decoder at z_s: m2,h2; x_star (direct store); delta,dsq
    dec_kernel<<<dim3(8,BB),256>>>(dec_W1, dec_b1, 1);
    gemm_k<64,128,16,4,8,false,false,1,1><<<dim3(96,1,1),256>>>(nullptr, dec_W2, HH, DD, DD, 2048);
    delta_kernel<<<dim3(48,BB),256>>>(x, dec_b2);

    // v = delta @ dec_W2^T, split-K24 (atomic into zeroed g_v)
    gemm_k<64,128,16,4,8,true,true,2,2><<<dim3(16,1,24),256>>>(nullptr, dec_W2, DD, DD, HH, 512);

    // T2, G2, t, final
    t_gemm_kernel<<<dim3(16,BB),128>>>(dec_W1, 1);
    g_kernel<<<BB,1024>>>(dec_W1, 1);
    t_kernel<<<BB,256>>>(dec_W1);
    final_kernel<<<1,64>>>(out);
}

// round 16
// speedup vs baseline: 3.1742x; 1.7072x over previous
#include <cuda_runtime.h>
#include <cuda_bf16.h>
#include <cstdint>

#define BB 64
#define DD 12288
#define NL 32
#define HH 2048

__device__ float g_h1[BB*HH];
__device__ float g_z1[BB*NL];
__device__ float g_zn[BB];
__device__ float g_sp[BB];
__device__ float g_sp2[BB], g_sv2[BB];
__device__ float g_sigterm[NL*NL];
__device__ float g_C[HH*HH];
__device__ float g_m1[BB*HH];
__device__ float g_m2[BB*HH];
__device__ float g_h2[BB*HH];
__device__ float g_T[BB*NL*HH];
__device__ float g_P[BB*NL*NL];
__device__ float g_G2[BB*NL*NL];
__device__ float g_zs[BB*NL];
__device__ float g_logdet[BB], g_trinv[BB];
__device__ float g_delta[BB*DD];
__device__ float g_dsq[BB];
__device__ float g_v[BB*HH];
__device__ float g_t[BB*NL];
__device__ __nv_bfloat16 g_w2bf[(size_t)HH*DD];   // bf16 dec_W2 (50MB)
__device__ __nv_bfloat16 g_cbf[(size_t)HH*HH];    // bf16 C (8MB)

union F2U { float2 f; unsigned long long u; };
__device__ __forceinline__ float2 f2fma(float2 a, float2 b, float2 c) {
    F2U A, Bv, Cv, R; A.f = a; Bv.f = b; Cv.f = c;
    asm("fma.rn.f32x2 %0, %1, %2, %3;" : "=l"(R.u) : "l"(A.u), "l"(Bv.u), "l"(Cv.u));
    return R.f;
}

__device__ __forceinline__ void mma16816(float* c, const uint32_t* a, const uint32_t* b) {
    asm volatile(
        "mma.sync.aligned.m16n8k16.row.col.f32.bf16.bf16.f32 "
        "{%0,%1,%2,%3}, {%4,%5,%6,%7}, {%8,%9}, {%0,%1,%2,%3};"
        : "+f"(c[0]), "+f"(c[1]), "+f"(c[2]), "+f"(c[3])
        : "r"(a[0]), "r"(a[1]), "r"(a[2]), "r"(a[3]), "r"(b[0]), "r"(b[1]));
}

// device-side operand binding (NEVER pass __device__ symbols from host)
template<int SEL> __device__ __forceinline__ const float* bindA(const float* A) {
    if (SEL == 1) return g_h2;
    if (SEL == 2) return g_delta;
    return A;
}
template<int SEL> __device__ __forceinline__ float* bindC() {
    if (SEL == 0) return g_h1;
    if (SEL == 1) return g_delta;
    return g_v;
}

__global__ void zero_kernel() {
    int i = blockIdx.x*blockDim.x + threadIdx.x;
    int tot = gridDim.x*blockDim.x;
    for (int k=i;k<BB*HH;k+=tot) { g_h1[k]=0.f; g_v[k]=0.f; }
    for (size_t k=i;k<(size_t)BB*DD;k+=tot) g_delta[k]=0.f;
    if (i<BB) g_dsq[i]=0.f;
}

// fp32 -> bf16 convert of dec_W2
__global__ __launch_bounds__(256) void w2bf_kernel(const float* __restrict__ W2) {
    size_t i = (size_t)blockIdx.x*256 + threadIdx.x;   // float4 index
    float4 v = ((const float4*)W2)[i];
    __nv_bfloat162 lo, hi;
    lo.x = __float2bfloat16(v.x); lo.y = __float2bfloat16(v.y);
    hi.x = __float2bfloat16(v.z); hi.y = __float2bfloat16(v.w);
    ((__nv_bfloat162*)g_w2bf)[2*i]   = lo;
    ((__nv_bfloat162*)g_w2bf)[2*i+1] = hi;
}

// fp32 -> bf16 convert of C
__global__ __launch_bounds__(256) void cbf_kernel() {
    size_t i = (size_t)blockIdx.x*256 + threadIdx.x;   // float4 index
    float4 v = ((const float4*)g_C)[i];
    __nv_bfloat162 lo, hi;
    lo.x = __float2bfloat16(v.x); lo.y = __float2bfloat16(v.y);
    hi.x = __float2bfloat16(v.z); hi.y = __float2bfloat16(v.w);
    ((__nv_bfloat162*)g_cbf)[2*i]   = lo;
    ((__nv_bfloat162*)g_cbf)[2*i+1] = hi;
}

// C = W2 W2^T upper 128x128 tiles via mma.sync bf16 (HMMA), fp32 accum.
__global__ __launch_bounds__(256) void syrk_mma_kernel() {
    __shared__ __nv_bfloat16 As[128*40];
    __shared__ __nv_bfloat16 Bs[128*40];
    const int tid = threadIdx.x, wid = tid>>5, lane = tid&31;
    const int gid = lane>>2, tig = lane&3;
    int p = blockIdx.x, ti = 0, cnt = 16;
    while (p >= cnt) { p -= cnt; cnt--; ti++; }
    const int tj = ti + p;
    const int wm = wid>>2, wn = wid&3;
    const __nv_bfloat16* Arows = g_w2bf + (size_t)ti*128*DD;
    const __nv_bfloat16* Brows = g_w2bf + (size_t)tj*128*DD;

    float acc[4][4][4];
    #pragma unroll
    for (int i=0;i<4;i++)
        #pragma unroll
        for (int j=0;j<4;j++)
            #pragma unroll
            for (int q=0;q<4;q++) acc[i][j][q]=0.f;

    for (int kb=0; kb<DD; kb+=32) {
        #pragma unroll
        for (int t=0;t<2;t++) {
            int u = tid + t*256;
            int row = u>>2, q = u&3;
            *(uint4*)&As[row*40+q*8] = *(const uint4*)(Arows + (size_t)row*DD + kb + q*8);
            *(uint4*)&Bs[row*40+q*8] = *(const uint4*)(Brows + (size_t)row*DD + kb + q*8);
        }
        __syncthreads();
        #pragma unroll
        for (int ks=0; ks<2; ks++) {
            const int k0 = ks*16;
            uint32_t afr[4][4], bfr[4][2];
            #pragma unroll
            for (int i=0;i<4;i++) {
                int r = wm*64 + i*16 + gid;
                afr[i][0] = *(const uint32_t*)&As[r*40     + k0 + 2*tig];
                afr[i][1] = *(const uint32_t*)&As[(r+8)*40 + k0 + 2*tig];
                afr[i][2] = *(const uint32_t*)&As[r*40     + k0 + 8 + 2*tig];
                afr[i][3] = *(const uint32_t*)&As[(r+8)*40 + k0 + 8 + 2*tig];
            }
            #pragma unroll
            for (int j=0;j<4;j++) {
                int c = wn*32 + j*8 + gid;
                bfr[j][0] = *(const uint32_t*)&Bs[c*40 + k0 + 2*tig];
                bfr[j][1] = *(const uint32_t*)&Bs[c*40 + k0 + 8 + 2*tig];
            }
            #pragma unroll
            for (int i=0;i<4;i++)
                #pragma unroll
                for (int j=0;j<4;j++)
                    mma16816(acc[i][j], afr[i], bfr[j]);
        }
        __syncthreads();
    }
    #pragma unroll
    for (int i=0;i<4;i++) {
        int r = ti*128 + wm*64 + i*16 + gid;
        #pragma unroll
        for (int j=0;j<4;j++) {
            int c = tj*128 + wn*32 + j*8 + 2*tig;
            *(float2*)&g_C[(size_t)r*HH + c]     = make_float2(acc[i][j][0], acc[i][j][1]);
            *(float2*)&g_C[(size_t)(r+8)*HH + c] = make_float2(acc[i][j][2], acc[i][j][3]);
        }
    }
}

// T[b] = (W1 .* m[b]) @ C via mma.sync. C symmetric: B fragment reads g_cbf rows K-major.
// CTA: 32x128 tile, 8 warps (wm in {0,1}: 16 rows; wn in {0..3}: 32 cols), K=HH.
__global__ __launch_bounds__(256) void t_gemm_mma_kernel(const float* __restrict__ W1, int useM2) {
    __shared__ __nv_bfloat16 As[32*40];
    __shared__ __nv_bfloat16 Bs[128*40];
    const int tid = threadIdx.x, wid = tid>>5, lane = tid&31;
    const int gid = lane>>2, tig = lane&3;
    const int b = blockIdx.y, col0 = blockIdx.x*128;
    const int wm = wid>>2, wn = wid&3;
    const float* mrow = (useM2 ? g_m2 : g_m1) + b*HH;

    float acc[4][4];
    #pragma unroll
    for (int j=0;j<4;j++)
        #pragma unroll
        for (int q=0;q<4;q++) acc[j][q]=0.f;

    for (int kb=0; kb<HH; kb+=32) {
        // A: 32 rows x 32 cols = 1024 bf16; thread -> row tid>>3, 4 cols
        {
            int r = tid>>3, c4 = (tid&7)*4;
            float4 w = *(const float4*)&W1[(size_t)r*HH + kb + c4];
            float4 m = *(const float4*)&mrow[kb + c4];
            __nv_bfloat162 lo, hi;
            lo.x = __float2bfloat16(w.x*m.x); lo.y = __float2bfloat16(w.y*m.y);
            hi.x = __float2bfloat16(w.z*m.z); hi.y = __float2bfloat16(w.w*m.w);
            *(__nv_bfloat162*)&As[r*40 + c4]     = lo;
            *(__nv_bfloat162*)&As[r*40 + c4 + 2] = hi;
        }
        // B: 128 rows (cols of T) x 32 cols (k); thread -> row tid>>1, 16 elems (two uint4)
        {
            int rr = tid>>1, base = (tid&1)*16;
            *(uint4*)&Bs[rr*40+base]   = *(const uint4*)&g_cbf[(size_t)(col0+rr)*HH + kb + base];
            *(uint4*)&Bs[rr*40+base+8] = *(const uint4*)&g_cbf[(size_t)(col0+rr)*HH + kb + base + 8];
        }
        __syncthreads();
        #pragma unroll
        for (int ks=0; ks<2; ks++) {
            const int k0 = ks*16;
            uint32_t afr[4], bfr[4][2];
            int r = wm*16 + gid;
            afr[0] = *(const uint32_t*)&As[r*40     + k0 + 2*tig];
            afr[1] = *(const uint32_t*)&As[(r+8)*40 + k0 + 2*tig];
            afr[2] = *(const uint32_t*)&As[r*40     + k0 + 8 + 2*tig];
            afr[3] = *(const uint32_t*)&As[(r+8)*40 + k0 + 8 + 2*tig];
            #pragma unroll
            for (int j=0;j<4;j++) {
                int c = wn*32 + j*8 + gid;
                bfr[j][0] = *(const uint32_t*)&Bs[c*40 + k0 + 2*tig];
                bfr[j][1] = *(const uint32_t*)&Bs[c*40 + k0 + 8 + 2*tig];
            }
            #pragma unroll
            for (int j=0;j<4;j++)
                mma16816(acc[j], afr, bfr[j]);
        }
        __syncthreads();
    }
    int n = wm*16 + gid;
    #pragma unroll
    for (int j=0;j<4;j++) {
        int c = col0 + wn*32 + j*8 + 2*tig;
        *(float2*)&g_T[(size_t)b*NL*HH + (size_t)n*HH + c]     = make_float2(acc[j][0], acc[j][1]);
        *(float2*)&g_T[(size_t)b*NL*HH + (size_t)(n+8)*HH + c] = make_float2(acc[j][2], acc[j][3]);
    }
}

// C[m][n] (+)= sum_k A[m*lda+k] * (BT ? B[n*ldb+k] : B[k*ldb+n])
template<int BM,int BN,int BK,int TM,int TN,bool BT,bool ACC,int ASEL,int CSEL>
__global__ __launch_bounds__((BM/TM)*(BN/TN))
void gemm_k(const float* __restrict__ Ain, const float* __restrict__ B,
            int lda, int ldb, int ldc, int kChunk) {
    const float* __restrict__ A = bindA<ASEL>(Ain);
    float* __restrict__ C = bindC<CSEL>();
    constexpr int THREADS = (BM/TM)*(BN/TN);
    __shared__ float As[BK][BM+4];
    __shared__ float Bs[BK][BN+4];
    const int tid = threadIdx.x;
    const int tx = tid % (BN/TN), ty = tid / (BN/TN);
    const int row0 = blockIdx.y*BM, col0 = blockIdx.x*BN;
    const int k0 = blockIdx.z*kChunk, k1 = k0 + kChunk;
    float2 acc[TM][TN/2];
    #pragma unroll
    for (int i=0;i<TM;i++)
        #pragma unroll
        for (int j=0;j<TN/2;j++) acc[i][j]=make_float2(0.f,0.f);
    for (int kb=k0; kb<k1; kb+=BK) {
        for (int i=tid;i<BM*BK;i+=THREADS) {
            int m=i/BK, kk=i%BK;
            As[kk][m] = A[(size_t)(row0+m)*lda + kb+kk];
        }
        if (!BT) {
            for (int i=tid;i<BK*BN;i+=THREADS) {
                int kk=i/BN, n=i%BN;
                Bs[kk][n] = B[(size_t)(kb+kk)*ldb + col0+n];
            }
        } else {
            for (int i=tid;i<BK*BN;i+=THREADS) {
                int n=i/BK, kk=i%BK;
                Bs[kk][n] = B[(size_t)(col0+n)*ldb + kb+kk];
            }
        }
        __syncthreads();
        #pragma unroll
        for (int kk=0;kk<BK;kk++) {
            float a[TM]; float2 bb[TN/2];
            #pragma unroll
            for (int i=0;i<TM;i++) a[i]=As[kk][ty*TM+i];
            #pragma unroll
            for (int j=0;j<TN/2;j++) bb[j]=*(const float2*)&Bs[kk][tx*TN+2*j];
            #pragma unroll
            for (int i=0;i<TM;i++) {
                float2 a2 = make_float2(a[i],a[i]);
                #pragma unroll
                for (int j=0;j<TN/2;j++) acc[i][j]=f2fma(a2,bb[j],acc[i][j]);
            }
        }
        __syncthreads();
    }
    #pragma unroll
    for (int i=0;i<TM;i++) {
        int gm = row0+ty*TM+i;
        #pragma unroll
        for (int j=0;j<TN/2;j++) {
            int gn = col0+tx*TN+2*j;
            if (ACC) {
                atomicAdd(&C[(size_t)gm*ldc+gn],   acc[i][j].x);
                atomicAdd(&C[(size_t)gm*ldc+gn+1], acc[i][j].y);
            } else {
                *(float2*)&C[(size_t)gm*ldc+gn] = acc[i][j];
            }
        }
    }
}

__global__ void relu_bias_kernel(const float* __restrict__ b1) {
    int i = blockIdx.x*blockDim.x + threadIdx.x;
    if (i < BB*HH) g_h1[i] = fmaxf(g_h1[i] + b1[i & (HH-1)], 0.f);
}

__global__ __launch_bounds__(256) void z1_kernel(const float* __restrict__ W2e, const float* __restrict__ b2e) {
    int b = blockIdx.x, tid = threadIdx.x;
    __shared__ float hrow[HH];
    __shared__ float red[8][NL];
    for (int i=tid;i<HH;i+=256) hrow[i]=g_h1[b*HH+i];
    __syncthreads();
    int n = tid & 31, s = tid >> 5;
    float acc=0.f;
    for (int h=s;h<HH;h+=8) acc = fmaf(hrow[h], W2e[h*NL+n], acc);
    red[s][n]=acc;
    __syncthreads();
    if (tid < NL) {
        float z = b2e[tid];
        #pragma unroll
        for (int ss=0;ss<8;ss++) z += red[ss][tid];
        g_z1[b*NL+tid]=z;
    }
}

__global__ void spsv_kernel(const float* __restrict__ sW, const float* __restrict__ sb) {
    int b = threadIdx.x;
    if (b >= BB) return;
    float a0=sb[0], zn=0.f;
    #pragma unroll
    for (int n=0;n<NL;n++) {
        float z = g_z1[b*NL+n];
        a0 = fmaf(z, sW[n*2], a0);
        zn = fmaf(z, z, zn);
    }
    g_sp[b]=expf(a0); g_zn[b]=zn;
}

__global__ void sigterm_kernel(const float* __restrict__ sW) {
    int i = threadIdx.x;
    int n = i >> 5, m = i & 31;
    g_sigterm[i] = 0.5f*((float)NL*sW[n*2]*sW[m*2] + (float)(DD-NL)*sW[n*2+1]*sW[m*2+1]);
}

__global__ __launch_bounds__(1024) void mirror_kernel() {
    int p = blockIdx.x, ti = 0, cnt = 64;
    while (p >= cnt) { p -= cnt; cnt--; ti++; }
    int tj = ti + p;
    int tx = threadIdx.x & 31, ty = threadIdx.x >> 5;
    int i0 = ti*32, j0 = tj*32;
    if (ti == tj) {
        int i = i0+ty, j = j0+tx;
        if (j > i) g_C[(size_t)j*HH+i] = g_C[(size_t)i*HH+j];
    } else {
        __shared__ float tile[32][33];
        tile[ty][tx] = g_C[(size_t)(i0+ty)*HH + j0+tx];
        __syncthreads();
        g_C[(size_t)(j0+ty)*HH + i0+tx] = tile[tx][ty];
    }
}

__global__ __launch_bounds__(256) void dec_kernel(const float* __restrict__ W1, const float* __restrict__ b1, int useZs) {
    int b = blockIdx.y;
    int h = blockIdx.x*256 + threadIdx.x;
    __shared__ float zs[NL];
    if (threadIdx.x < NL) zs[threadIdx.x] = useZs ? g_zs[b*NL+threadIdx.x] : g_z1[b*NL+threadIdx.x];
    __syncthreads();
    float acc = b1[h];
    #pragma unroll
    for (int n=0;n<NL;n++) acc = fmaf(zs[n], W1[n*HH+h], acc);
    if (useZs) {
        g_m2[b*HH+h] = acc>0.f?1.f:0.f;
        g_h2[b*HH+h] = fmaxf(acc, 0.f);
    } else {
        g_m1[b*HH+h] = acc>0.f?1.f:0.f;
    }
}

__global__ __launch_bounds__(1024) void g_kernel(const float* __restrict__ W1, int mode) {
    int b = blockIdx.x;
    int tx = threadIdx.x & 31, ty = threadIdx.x >> 5;
    const float* mrow = (mode ? g_m2 : g_m1) + b*HH;
    __shared__ float Ts[32][33], Ws[32][33];
    float acc = 0.f;
    for (int j0=0;j0<HH;j0+=32) {
        Ts[ty][tx] = g_T[(size_t)b*NL*HH + ty*HH + j0+tx];
        Ws[ty][tx] = W1[ty*HH + j0+tx]*mrow[j0+tx];
        __syncthreads();
        #pragma unroll
        for (int jj=0;jj<32;jj++) acc = fmaf(Ts[ty][jj], Ws[tx][jj], acc);
        __syncthreads();
    }
    if (mode == 0) {
        float sp = g_sp[b];
        float val = acc/(sp*sp) + g_sigterm[ty*NL+tx] + (tx==ty ? 1.f : 0.f);
        g_P[b*NL*NL + ty*NL + tx] = val;
    } else {
        g_G2[b*NL*NL + ty*NL + tx] = acc;
    }
}

__device__ void chol32_serial(float A[NL][NL]) {
    for (int k=0;k<NL;k++) {
        A[k][k] = sqrtf(A[k][k]);
        float inv = 1.f/A[k][k];
        for (int i=k+1;i<NL;i++) A[i][k] *= inv;
        for (int i=k+1;i<NL;i++) {
            float lik = A[i][k];
            for (int j=k+1;j<=i;j++) A[i][j] -= lik*A[j][k];
        }
    }
}

__global__ void chol_prec_kernel(const float* __restrict__ eps, const float* __restrict__ sW, const float* __restrict__ sb) {
    int b = blockIdx.x*blockDim.x + threadIdx.x;
    if (b >= BB) return;
    float A[NL][NL];
    for (int i=0;i<NL;i++)
        for (int j=0;j<=i;j++) A[i][j] = g_P[b*NL*NL + i*NL + j];
    chol32_serial(A);
    float ld = 0.f;
    for (int k=0;k<NL;k++) ld += logf(A[k][k]);
    float tr = 0.f;
    float X[NL];
    for (int c=0;c<NL;c++) {
        X[c] = 1.f/A[c][c];
        tr += X[c]*X[c];
        for (int i=c+1;i<NL;i++) {
            float s = 0.f;
            for (int j=c;j<i;j++) s += A[i][j]*X[j];
            X[i] = -s/A[i][i];
            tr += X[i]*X[i];
        }
    }
    float dz[NL];
    for (int k=NL-1;k>=0;k--) {
        float s = eps[b*NL+k];
        for (int j=k+1;j<NL;j++) s -= A[j][k]*dz[j];
        dz[k] = s/A[k][k];
    }
    float a0 = sb[0], a1 = sb[1];
    for (int n=0;n<NL;n++) {
        float zs = g_z1[b*NL+n] + dz[n];
        g_zs[b*NL+n] = zs;
        a0 = fmaf(zs, sW[n*2],   a0);
        a1 = fmaf(zs, sW[n*2+1], a1);
    }
    g_logdet[b] = ld;
    g_trinv[b] = tr;
    g_sp2[b] = expf(a0);
    g_sv2[b] = expf(a1);
}

__global__ __launch_bounds__(256) void delta_kernel(const float* __restrict__ x, const float* __restrict__ b2) {
    int b = blockIdx.y;
    int d = blockIdx.x*256 + threadIdx.x;
    float del = x[(size_t)b*DD+d] - (g_delta[(size_t)b*DD+d] + b2[d]);
    g_delta[(size_t)b*DD+d] = del;
    __shared__ float red[256];
    red[threadIdx.x] = del*del;
    __syncthreads();
    for (int s=128;s;s>>=1) { if (threadIdx.x<s) red[threadIdx.x]+=red[threadIdx.x+s]; __syncthreads(); }
    if (threadIdx.x==0) atomicAdd(&g_dsq[b], red[0]);
}

__global__ __launch_bounds__(256) void t_kernel(const float* __restrict__ W1) {
    int b = blockIdx.x, tid = threadIdx.x;
    int lane = tid & 31, s = tid >> 5;
    __shared__ float p[HH];
    for (int i=tid;i<HH;i+=256) p[i] = g_m2[b*HH+i]*g_v[b*HH+i];
    __syncthreads();
    #pragma unroll
    for (int nn=0; nn<4; nn++) {
        int n = s*4+nn;
        float acc = 0.f;
        for (int h=lane; h<HH; h+=32) acc = fmaf(p[h], W1[n*HH+h], acc);
        #pragma unroll
        for (int o=16;o;o>>=1) acc += __shfl_xor_sync(0xffffffffu, acc, o);
        if (lane==0) g_t[b*NL+n]=acc;
    }
}

__global__ void final_kernel(float* __restrict__ out) {
    int b = blockIdx.x*blockDim.x + threadIdx.x;
    if (b >= BB) return;
    float A[NL][NL];
    for (int i=0;i<NL;i++)
        for (int j=0;j<=i;j++) A[i][j] = g_G2[b*NL*NL + i*NL + j];
    chol32_serial(A);
    float y[NL];
    float dp = 0.f;
    for (int k=0;k<NL;k++) {
        float s = g_t[b*NL+k];
        for (int j=0;j<k;j++) s -= A[k][j]*y[j];
        y[k] = s/A[k][k];
        dp += y[k]*y[k];
    }
    float sp2 = g_sp2[b], sv2 = g_sv2[b];
    float recon = g_dsq[b]/(2.f*sv2*sv2)
                + dp*(0.5f/(sp2*sp2) - 0.5f/(sv2*sv2))
                + (float)NL*logf(sp2) + (float)(DD-NL)*logf(sv2);
    float latent = 0.5f*g_zn[b] + 0.5f*g_trinv[b];
    out[b] = (recon + latent + g_logdet[b]) / (float)DD;
}

extern "C" void kernel_launch(void* const* d_in, const int* in_sizes, int n_in,
                              void* d_out, int out_size) {
    const float* x      = (const float*)d_in[0];
    const float* eps    = (const float*)d_in[1];
    const float* enc_W1 = (const float*)d_in[2];
    const float* enc_b1 = (const float*)d_in[3];
    const float* enc_W2 = (const float*)d_in[4];
    const float* enc_b2 = (const float*)d_in[5];
    const float* dec_W1 = (const float*)d_in[6];
    const float* dec_b1 = (const float*)d_in[7];
    const float* dec_W2 = (const float*)d_in[8];
    const float* dec_b2 = (const float*)d_in[9];
    const float* sig_W  = (const float*)d_in[10];
    const float* sig_b  = (const float*)d_in[11];
    float* out = (float*)d_out;

    zero_kernel<<<256,256>>>();

    // bf16 dec_W2; HMMA syrk (upper tiles); mirror; bf16 C
    w2bf_kernel<<<(HH*DD/4)/256,256>>>(dec_W2);
    syrk_mma_kernel<<<136,256>>>();
    mirror_kernel<<<2080,1024>>>();
    cbf_kernel<<<(HH*HH/4)/256,256>>>();

    // encoder: h1 = x @ enc_W1, split-K24 (atomic into zeroed g_h1)
    gemm_k<64,128,16,4,8,false,true,0,0><<<dim3(16,1,24),256>>>(x, enc_W1, DD, HH, HH, 512);
    relu_bias_kernel<<<(BB*HH)/256,256>>>(enc_b1);
    z1_kernel<<<BB,256>>>(enc_W2, enc_b2);
    spsv_kernel<<<1,64>>>(sig_W, sig_b);
    sigterm_kernel<<<1,1024>>>(sig_W);

    // m1; T1 = (W1.*m1)@C (HMMA); Prec
    dec_kernel<<<dim3(8,BB),256>>>(dec_W1, dec_b1, 0);
    t_gemm_mma_kernel<<<dim3(16,BB),256>>>(dec_W1, 0);
    g_kernel<<<BB,1024>>>(dec_W1, 0);

    chol_prec_kernel<<<1,64>>>(eps, sig_W, sig_b);

    // decoder at z_s: m2,h2; x_star split-K4 (atomic into zeroed g_delta); delta,dsq
    dec_kernel<<<dim3(8,BB),256>>>(dec_W1, dec_b1, 1);
    gemm_k<64,128,16,4,8,false,true,1,1><<<dim3(96,1,4),256>>>(nullptr, dec_W2, HH, DD, DD, 512);
    delta_kernel<<<dim3(48,BB),256>>>(x, dec_b2);

    // v = delta @ dec_W2^T, split-K24 (atomic into zeroed g_v)
    gemm_k<64,128,16,4,8,true,true,2,2><<<dim3(16,1,24),256>>>(nullptr, dec_W2, DD, DD, HH, 512);

    // T2 (HMMA), G2, t, final
    t_gemm_mma_kernel<<<dim3(16,BB),256>>>(dec_W1, 1);
    g_kernel<<<BB,1024>>>(dec_W1, 1);
    t_kernel<<<BB,256>>>(dec_W1);
    final_kernel<<<1,64>>>(out);
}

// round 17
// speedup vs baseline: 3.7444x; 1.1796x over previous
#include <cuda_runtime.h>
#include <cuda_bf16.h>
#include <cstdint>

#define BB 64
#define DD 12288
#define NL 32
#define HH 2048

__device__ float g_h1[BB*HH];
__device__ float g_z1[BB*NL];
__device__ float g_zn[BB];
__device__ float g_sp[BB];
__device__ float g_sp2[BB], g_sv2[BB];
__device__ float g_sigterm[NL*NL];
__device__ float g_C[HH*HH];
__device__ float g_m1[BB*HH];
__device__ float g_m2[BB*HH];
__device__ float g_h2[BB*HH];
__device__ float g_T[BB*NL*HH];
__device__ float g_P[BB*NL*NL];
__device__ float g_G2[BB*NL*NL];
__device__ float g_zs[BB*NL];
__device__ float g_logdet[BB], g_trinv[BB];
__device__ float g_delta[BB*DD];
__device__ float g_dsq[BB];
__device__ float g_v[BB*HH];
__device__ float g_t[BB*NL];
__device__ __nv_bfloat16 g_w2bf[(size_t)HH*DD];   // bf16 dec_W2 [HH][DD]
__device__ __nv_bfloat16 g_cbf[(size_t)HH*HH];    // bf16 C
__device__ __nv_bfloat16 g_w1et[(size_t)HH*DD];   // bf16 enc_W1^T [HH][DD]
__device__ __nv_bfloat16 g_w2t[(size_t)DD*HH];    // bf16 dec_W2^T [DD][HH]

__device__ __forceinline__ void mma16816(float* c, const uint32_t* a, const uint32_t* b) {
    asm volatile(
        "mma.sync.aligned.m16n8k16.row.col.f32.bf16.bf16.f32 "
        "{%0,%1,%2,%3}, {%4,%5,%6,%7}, {%8,%9}, {%0,%1,%2,%3};"
        : "+f"(c[0]), "+f"(c[1]), "+f"(c[2]), "+f"(c[3])
        : "r"(a[0]), "r"(a[1]), "r"(a[2]), "r"(a[3]), "r"(b[0]), "r"(b[1]));
}

// device-side operand binding (NEVER pass __device__ symbols from host)
template<int SEL> __device__ __forceinline__ const float* bindA(const float* A) {
    if (SEL == 1) return g_h2;
    if (SEL == 2) return g_delta;
    return A;
}
template<int SEL> __device__ __forceinline__ const __nv_bfloat16* bindB() {
    if (SEL == 0) return g_w1et;
    if (SEL == 1) return g_w2t;
    return g_w2bf;
}
template<int SEL> __device__ __forceinline__ float* bindC() {
    if (SEL == 0) return g_h1;
    if (SEL == 1) return g_delta;
    return g_v;
}
template<int SEL> __device__ __forceinline__ __nv_bfloat16* bindT() {
    if (SEL == 0) return g_w1et;
    return g_w2t;
}

__global__ void zero_kernel() {
    int i = blockIdx.x*blockDim.x + threadIdx.x;
    int tot = gridDim.x*blockDim.x;
    for (int k=i;k<BB*HH;k+=tot) { g_h1[k]=0.f; g_v[k]=0.f; }
    for (size_t k=i;k<(size_t)BB*DD;k+=tot) g_delta[k]=0.f;
    if (i<BB) g_dsq[i]=0.f;
}

// fp32 -> bf16 convert of dec_W2 (row-major copy)
__global__ __launch_bounds__(256) void w2bf_kernel(const float* __restrict__ W2) {
    size_t i = (size_t)blockIdx.x*256 + threadIdx.x;
    float4 v = ((const float4*)W2)[i];
    __nv_bfloat162 lo, hi;
    lo.x = __float2bfloat16(v.x); lo.y = __float2bfloat16(v.y);
    hi.x = __float2bfloat16(v.z); hi.y = __float2bfloat16(v.w);
    ((__nv_bfloat162*)g_w2bf)[2*i]   = lo;
    ((__nv_bfloat162*)g_w2bf)[2*i+1] = hi;
}

// fp32 -> bf16 convert of C
__global__ __launch_bounds__(256) void cbf_kernel() {
    size_t i = (size_t)blockIdx.x*256 + threadIdx.x;
    float4 v = ((const float4*)g_C)[i];
    __nv_bfloat162 lo, hi;
    lo.x = __float2bfloat16(v.x); lo.y = __float2bfloat16(v.y);
    hi.x = __float2bfloat16(v.z); hi.y = __float2bfloat16(v.w);
    ((__nv_bfloat162*)g_cbf)[2*i]   = lo;
    ((__nv_bfloat162*)g_cbf)[2*i+1] = hi;
}

// transpose + bf16 convert: dst[c][r] = bf16(src[r][c]); src is R x Ccols row-major
template<int DSEL>
__global__ __launch_bounds__(256) void convT_kernel(const float* __restrict__ src, int R, int Ccols) {
    __nv_bfloat16* dst = bindT<DSEL>();
    __shared__ float tile[32][33];
    int c0 = blockIdx.x*32, r0 = blockIdx.y*32;
    int tx = threadIdx.x & 31, ty = threadIdx.x >> 5;  // 32 x 8
    #pragma unroll
    for (int i=0;i<32;i+=8)
        tile[ty+i][tx] = src[(size_t)(r0+ty+i)*Ccols + c0+tx];
    __syncthreads();
    #pragma unroll
    for (int i=0;i<32;i+=8)
        dst[(size_t)(c0+ty+i)*R + r0+tx] = __float2bfloat16(tile[tx][ty+i]);
}

// C = W2 W2^T upper 128x128 tiles via mma.sync bf16 (HMMA), fp32 accum.
__global__ __launch_bounds__(256) void syrk_mma_kernel() {
    __shared__ __nv_bfloat16 As[128*40];
    __shared__ __nv_bfloat16 Bs[128*40];
    const int tid = threadIdx.x, wid = tid>>5, lane = tid&31;
    const int gid = lane>>2, tig = lane&3;
    int p = blockIdx.x, ti = 0, cnt = 16;
    while (p >= cnt) { p -= cnt; cnt--; ti++; }
    const int tj = ti + p;
    const int wm = wid>>2, wn = wid&3;
    const __nv_bfloat16* Arows = g_w2bf + (size_t)ti*128*DD;
    const __nv_bfloat16* Brows = g_w2bf + (size_t)tj*128*DD;

    float acc[4][4][4];
    #pragma unroll
    for (int i=0;i<4;i++)
        #pragma unroll
        for (int j=0;j<4;j++)
            #pragma unroll
            for (int q=0;q<4;q++) acc[i][j][q]=0.f;

    for (int kb=0; kb<DD; kb+=32) {
        #pragma unroll
        for (int t=0;t<2;t++) {
            int u = tid + t*256;
            int row = u>>2, q = u&3;
            *(uint4*)&As[row*40+q*8] = *(const uint4*)(Arows + (size_t)row*DD + kb + q*8);
            *(uint4*)&Bs[row*40+q*8] = *(const uint4*)(Brows + (size_t)row*DD + kb + q*8);
        }
        __syncthreads();
        #pragma unroll
        for (int ks=0; ks<2; ks++) {
            const int k0 = ks*16;
            uint32_t afr[4][4], bfr[4][2];
            #pragma unroll
            for (int i=0;i<4;i++) {
                int r = wm*64 + i*16 + gid;
                afr[i][0] = *(const uint32_t*)&As[r*40     + k0 + 2*tig];
                afr[i][1] = *(const uint32_t*)&As[(r+8)*40 + k0 + 2*tig];
                afr[i][2] = *(const uint32_t*)&As[r*40     + k0 + 8 + 2*tig];
                afr[i][3] = *(const uint32_t*)&As[(r+8)*40 + k0 + 8 + 2*tig];
            }
            #pragma unroll
            for (int j=0;j<4;j++) {
                int c = wn*32 + j*8 + gid;
                bfr[j][0] = *(const uint32_t*)&Bs[c*40 + k0 + 2*tig];
                bfr[j][1] = *(const uint32_t*)&Bs[c*40 + k0 + 8 + 2*tig];
            }
            #pragma unroll
            for (int i=0;i<4;i++)
                #pragma unroll
                for (int j=0;j<4;j++)
                    mma16816(acc[i][j], afr[i], bfr[j]);
        }
        __syncthreads();
    }
    #pragma unroll
    for (int i=0;i<4;i++) {
        int r = ti*128 + wm*64 + i*16 + gid;
        #pragma unroll
        for (int j=0;j<4;j++) {
            int c = tj*128 + wn*32 + j*8 + 2*tig;
            *(float2*)&g_C[(size_t)r*HH + c]     = make_float2(acc[i][j][0], acc[i][j][1]);
            *(float2*)&g_C[(size_t)(r+8)*HH + c] = make_float2(acc[i][j][2], acc[i][j][3]);
        }
    }
}

// T[b] = (W1 .* m[b]) @ C via mma.sync (C symmetric, B reads g_cbf rows K-major).
__global__ __launch_bounds__(256) void t_gemm_mma_kernel(const float* __restrict__ W1, int useM2) {
    __shared__ __nv_bfloat16 As[32*40];
    __shared__ __nv_bfloat16 Bs[128*40];
    const int tid = threadIdx.x, wid = tid>>5, lane = tid&31;
    const int gid = lane>>2, tig = lane&3;
    const int b = blockIdx.y, col0 = blockIdx.x*128;
    const int wm = wid>>2, wn = wid&3;
    const float* mrow = (useM2 ? g_m2 : g_m1) + b*HH;

    float acc[4][4];
    #pragma unroll
    for (int j=0;j<4;j++)
        #pragma unroll
        for (int q=0;q<4;q++) acc[j][q]=0.f;

    for (int kb=0; kb<HH; kb+=32) {
        {
            int r = tid>>3, c4 = (tid&7)*4;
            float4 w = *(const float4*)&W1[(size_t)r*HH + kb + c4];
            float4 m = *(const float4*)&mrow[kb + c4];
            __nv_bfloat162 lo, hi;
            lo.x = __float2bfloat16(w.x*m.x); lo.y = __float2bfloat16(w.y*m.y);
            hi.x = __float2bfloat16(w.z*m.z); hi.y = __float2bfloat16(w.w*m.w);
            *(__nv_bfloat162*)&As[r*40 + c4]     = lo;
            *(__nv_bfloat162*)&As[r*40 + c4 + 2] = hi;
        }
        {
            int rr = tid>>1, base = (tid&1)*16;
            *(uint4*)&Bs[rr*40+base]   = *(const uint4*)&g_cbf[(size_t)(col0+rr)*HH + kb + base];
            *(uint4*)&Bs[rr*40+base+8] = *(const uint4*)&g_cbf[(size_t)(col0+rr)*HH + kb + base + 8];
        }
        __syncthreads();
        #pragma unroll
        for (int ks=0; ks<2; ks++) {
            const int k0 = ks*16;
            uint32_t afr[4], bfr[4][2];
            int r = wm*16 + gid;
            afr[0] = *(const uint32_t*)&As[r*40     + k0 + 2*tig];
            afr[1] = *(const uint32_t*)&As[(r+8)*40 + k0 + 2*tig];
            afr[2] = *(const uint32_t*)&As[r*40     + k0 + 8 + 2*tig];
            afr[3] = *(const uint32_t*)&As[(r+8)*40 + k0 + 8 + 2*tig];
            #pragma unroll
            for (int j=0;j<4;j++) {
                int c = wn*32 + j*8 + gid;
                bfr[j][0] = *(const uint32_t*)&Bs[c*40 + k0 + 2*tig];
                bfr[j][1] = *(const uint32_t*)&Bs[c*40 + k0 + 8 + 2*tig];
            }
            #pragma unroll
            for (int j=0;j<4;j++)
                mma16816(acc[j], afr, bfr[j]);
        }
        __syncthreads();
    }
    int n = wm*16 + gid;
    #pragma unroll
    for (int j=0;j<4;j++) {
        int c = col0 + wn*32 + j*8 + 2*tig;
        *(float2*)&g_T[(size_t)b*NL*HH + (size_t)n*HH + c]     = make_float2(acc[j][0], acc[j][1]);
        *(float2*)&g_T[(size_t)b*NL*HH + (size_t)(n+8)*HH + c] = make_float2(acc[j][2], acc[j][3]);
    }
}

// Generic: C[64][N] += bf16(Afp32[64][K]) @ Bbf[N][K]^T  (split-K, atomic accumulate).
// lda = ldb = K; ldc = N_total. Block 64x128 tile; 8 warps (wm 0..1 -> 32 rows, wn 0..3).
template<int ASEL,int BSEL,int CSEL>
__global__ __launch_bounds__(256) void hmma64_kernel(const float* __restrict__ Ain,
                                                     int K, int ldc, int kChunk) {
    const float* __restrict__ A = bindA<ASEL>(Ain);
    const __nv_bfloat16* __restrict__ B = bindB<BSEL>();
    float* __restrict__ C = bindC<CSEL>();
    __shared__ __nv_bfloat16 As[64*40];
    __shared__ __nv_bfloat16 Bs[128*40];
    const int tid = threadIdx.x, wid = tid>>5, lane = tid&31;
    const int gid = lane>>2, tig = lane&3;
    const int col0 = blockIdx.x*128;
    const int kbeg = blockIdx.z*kChunk, kend = kbeg + kChunk;
    const int wm = wid>>2, wn = wid&3;

    float acc[2][4][4];
    #pragma unroll
    for (int i=0;i<2;i++)
        #pragma unroll
        for (int j=0;j<4;j++)
            #pragma unroll
            for (int q=0;q<4;q++) acc[i][j][q]=0.f;

    for (int kb=kbeg; kb<kend; kb+=32) {
        // A: 64 rows x 32 k = 2048; thread -> row tid>>2, 8 cols at (tid&3)*8
        {
            int r = tid>>2, c8 = (tid&3)*8;
            float4 v0 = *(const float4*)&A[(size_t)r*K + kb + c8];
            float4 v1 = *(const float4*)&A[(size_t)r*K + kb + c8 + 4];
            __nv_bfloat162 p0, p1, p2, p3;
            p0.x=__float2bfloat16(v0.x); p0.y=__float2bfloat16(v0.y);
            p1.x=__float2bfloat16(v0.z); p1.y=__float2bfloat16(v0.w);
            p2.x=__float2bfloat16(v1.x); p2.y=__float2bfloat16(v1.y);
            p3.x=__float2bfloat16(v1.z); p3.y=__float2bfloat16(v1.w);
            *(__nv_bfloat162*)&As[r*40 + c8]     = p0;
            *(__nv_bfloat162*)&As[r*40 + c8 + 2] = p1;
            *(__nv_bfloat162*)&As[r*40 + c8 + 4] = p2;
            *(__nv_bfloat162*)&As[r*40 + c8 + 6] = p3;
        }
        // B: 128 rows x 32 k; thread -> row tid>>1, 16 elems (two uint4)
        {
            int rr = tid>>1, base = (tid&1)*16;
            *(uint4*)&Bs[rr*40+base]   = *(const uint4*)&B[(size_t)(col0+rr)*K + kb + base];
            *(uint4*)&Bs[rr*40+base+8] = *(const uint4*)&B[(size_t)(col0+rr)*K + kb + base + 8];
        }
        __syncthreads();
        #pragma unroll
        for (int ks=0; ks<2; ks++) {
            const int k0 = ks*16;
            uint32_t afr[2][4], bfr[4][2];
            #pragma unroll
            for (int i=0;i<2;i++) {
                int r = wm*32 + i*16 + gid;
                afr[i][0] = *(const uint32_t*)&As[r*40     + k0 + 2*tig];
                afr[i][1] = *(const uint32_t*)&As[(r+8)*40 + k0 + 2*tig];
                afr[i][2] = *(const uint32_t*)&As[r*40     + k0 + 8 + 2*tig];
                afr[i][3] = *(const uint32_t*)&As[(r+8)*40 + k0 + 8 + 2*tig];
            }
            #pragma unroll
            for (int j=0;j<4;j++) {
                int c = wn*32 + j*8 + gid;
                bfr[j][0] = *(const uint32_t*)&Bs[c*40 + k0 + 2*tig];
                bfr[j][1] = *(const uint32_t*)&Bs[c*40 + k0 + 8 + 2*tig];
            }
            #pragma unroll
            for (int i=0;i<2;i++)
                #pragma unroll
                for (int j=0;j<4;j++)
                    mma16816(acc[i][j], afr[i], bfr[j]);
        }
        __syncthreads();
    }
    #pragma unroll
    for (int i=0;i<2;i++) {
        int r = wm*32 + i*16 + gid;
        #pragma unroll
        for (int j=0;j<4;j++) {
            int c = col0 + wn*32 + j*8 + 2*tig;
            atomicAdd(&C[(size_t)r*ldc + c],            acc[i][j][0]);
            atomicAdd(&C[(size_t)r*ldc + c + 1],        acc[i][j][1]);
            atomicAdd(&C[(size_t)(r+8)*ldc + c],        acc[i][j][2]);
            atomicAdd(&C[(size_t)(r+8)*ldc + c + 1],    acc[i][j][3]);
        }
    }
}

__global__ void relu_bias_kernel(const float* __restrict__ b1) {
    int i = blockIdx.x*blockDim.x + threadIdx.x;
    if (i < BB*HH) g_h1[i] = fmaxf(g_h1[i] + b1[i & (HH-1)], 0.f);
}

__global__ __launch_bounds__(256) void z1_kernel(const float* __restrict__ W2e, const float* __restrict__ b2e) {
    int b = blockIdx.x, tid = threadIdx.x;
    __shared__ float hrow[HH];
    __shared__ float red[8][NL];
    for (int i=tid;i<HH;i+=256) hrow[i]=g_h1[b*HH+i];
    __syncthreads();
    int n = tid & 31, s = tid >> 5;
    float acc=0.f;
    for (int h=s;h<HH;h+=8) acc = fmaf(hrow[h], W2e[h*NL+n], acc);
    red[s][n]=acc;
    __syncthreads();
    if (tid < NL) {
        float z = b2e[tid];
        #pragma unroll
        for (int ss=0;ss<8;ss++) z += red[ss][tid];
        g_z1[b*NL+tid]=z;
    }
}

__global__ void spsv_kernel(const float* __restrict__ sW, const float* __restrict__ sb) {
    int b = threadIdx.x;
    if (b >= BB) return;
    float a0=sb[0], zn=0.f;
    #pragma unroll
    for (int n=0;n<NL;n++) {
        float z = g_z1[b*NL+n];
        a0 = fmaf(z, sW[n*2], a0);
        zn = fmaf(z, z, zn);
    }
    g_sp[b]=expf(a0); g_zn[b]=zn;
}

__global__ void sigterm_kernel(const float* __restrict__ sW) {
    int i = threadIdx.x;
    int n = i >> 5, m = i & 31;
    g_sigterm[i] = 0.5f*((float)NL*sW[n*2]*sW[m*2] + (float)(DD-NL)*sW[n*2+1]*sW[m*2+1]);
}

__global__ __launch_bounds__(1024) void mirror_kernel() {
    int p = blockIdx.x, ti = 0, cnt = 64;
    while (p >= cnt) { p -= cnt; cnt--; ti++; }
    int tj = ti + p;
    int tx = threadIdx.x & 31, ty = threadIdx.x >> 5;
    int i0 = ti*32, j0 = tj*32;
    if (ti == tj) {
        int i = i0+ty, j = j0+tx;
        if (j > i) g_C[(size_t)j*HH+i] = g_C[(size_t)i*HH+j];
    } else {
        __shared__ float tile[32][33];
        tile[ty][tx] = g_C[(size_t)(i0+ty)*HH + j0+tx];
        __syncthreads();
        g_C[(size_t)(j0+ty)*HH + i0+tx] = tile[tx][ty];
    }
}

__global__ __launch_bounds__(256) void dec_kernel(const float* __restrict__ W1, const float* __restrict__ b1, int useZs) {
    int b = blockIdx.y;
    int h = blockIdx.x*256 + threadIdx.x;
    __shared__ float zs[NL];
    if (threadIdx.x < NL) zs[threadIdx.x] = useZs ? g_zs[b*NL+threadIdx.x] : g_z1[b*NL+threadIdx.x];
    __syncthreads();
    float acc = b1[h];
    #pragma unroll
    for (int n=0;n<NL;n++) acc = fmaf(zs[n], W1[n*HH+h], acc);
    if (useZs) {
        g_m2[b*HH+h] = acc>0.f?1.f:0.f;
        g_h2[b*HH+h] = fmaxf(acc, 0.f);
    } else {
        g_m1[b*HH+h] = acc>0.f?1.f:0.f;
    }
}

__global__ __launch_bounds__(1024) void g_kernel(const float* __restrict__ W1, int mode) {
    int b = blockIdx.x;
    int tx = threadIdx.x & 31, ty = threadIdx.x >> 5;
    const float* mrow = (mode ? g_m2 : g_m1) + b*HH;
    __shared__ float Ts[32][33], Ws[32][33];
    float acc = 0.f;
    for (int j0=0;j0<HH;j0+=32) {
        Ts[ty][tx] = g_T[(size_t)b*NL*HH + ty*HH + j0+tx];
        Ws[ty][tx] = W1[ty*HH + j0+tx]*mrow[j0+tx];
        __syncthreads();
        #pragma unroll
        for (int jj=0;jj<32;jj++) acc = fmaf(Ts[ty][jj], Ws[tx][jj], acc);
        __syncthreads();
    }
    if (mode == 0) {
        float sp = g_sp[b];
        float val = acc/(sp*sp) + g_sigterm[ty*NL+tx] + (tx==ty ? 1.f : 0.f);
        g_P[b*NL*NL + ty*NL + tx] = val;
    } else {
        g_G2[b*NL*NL + ty*NL + tx] = acc;
    }
}

__device__ void chol32_serial(float A[NL][NL]) {
    for (int k=0;k<NL;k++) {
        A[k][k] = sqrtf(A[k][k]);
        float inv = 1.f/A[k][k];
        for (int i=k+1;i<NL;i++) A[i][k] *= inv;
        for (int i=k+1;i<NL;i++) {
            float lik = A[i][k];
            for (int j=k+1;j<=i;j++) A[i][j] -= lik*A[j][k];
        }
    }
}

__global__ void chol_prec_kernel(const float* __restrict__ eps, const float* __restrict__ sW, const float* __restrict__ sb) {
    int b = blockIdx.x*blockDim.x + threadIdx.x;
    if (b >= BB) return;
    float A[NL][NL];
    for (int i=0;i<NL;i++)
        for (int j=0;j<=i;j++) A[i][j] = g_P[b*NL*NL + i*NL + j];
    chol32_serial(A);
    float ld = 0.f;
    for (int k=0;k<NL;k++) ld += logf(A[k][k]);
    float tr = 0.f;
    float X[NL];
    for (int c=0;c<NL;c++) {
        X[c] = 1.f/A[c][c];
        tr += X[c]*X[c];
        for (int i=c+1;i<NL;i++) {
            float s = 0.f;
            for (int j=c;j<i;j++) s += A[i][j]*X[j];
            X[i] = -s/A[i][i];
            tr += X[i]*X[i];
        }
    }
    float dz[NL];
    for (int k=NL-1;k>=0;k--) {
        float s = eps[b*NL+k];
        for (int j=k+1;j<NL;j++) s -= A[j][k]*dz[j];
        dz[k] = s/A[k][k];
    }
    float a0 = sb[0], a1 = sb[1];
    for (int n=0;n<NL;n++) {
        float zs = g_z1[b*NL+n] + dz[n];
        g_zs[b*NL+n] = zs;
        a0 = fmaf(zs, sW[n*2],   a0);
        a1 = fmaf(zs, sW[n*2+1], a1);
    }
    g_logdet[b] = ld;
    g_trinv[b] = tr;
    g_sp2[b] = expf(a0);
    g_sv2[b] = expf(a1);
}

__global__ __launch_bounds__(256) void delta_kernel(const float* __restrict__ x, const float* __restrict__ b2) {
    int b = blockIdx.y;
    int d = blockIdx.x*256 + threadIdx.x;
    float del = x[(size_t)b*DD+d] - (g_delta[(size_t)b*DD+d] + b2[d]);
    g_delta[(size_t)b*DD+d] = del;
    __shared__ float red[256];
    red[threadIdx.x] = del*del;
    __syncthreads();
    for (int s=128;s;s>>=1) { if (threadIdx.x<s) red[threadIdx.x]+=red[threadIdx.x+s]; __syncthreads(); }
    if (threadIdx.x==0) atomicAdd(&g_dsq[b], red[0]);
}

__global__ __launch_bounds__(256) void t_kernel(const float* __restrict__ W1) {
    int b = blockIdx.x, tid = threadIdx.x;
    int lane = tid & 31, s = tid >> 5;
    __shared__ float p[HH];
    for (int i=tid;i<HH;i+=256) p[i] = g_m2[b*HH+i]*g_v[b*HH+i];
    __syncthreads();
    #pragma unroll
    for (int nn=0; nn<4; nn++) {
        int n = s*4+nn;
        float acc = 0.f;
        for (int h=lane; h<HH; h+=32) acc = fmaf(p[h], W1[n*HH+h], acc);
        #pragma unroll
        for (int o=16;o;o>>=1) acc += __shfl_xor_sync(0xffffffffu, acc, o);
        if (lane==0) g_t[b*NL+n]=acc;
    }
}

__global__ void final_kernel(float* __restrict__ out) {
    int b = blockIdx.x*blockDim.x + threadIdx.x;
    if (b >= BB) return;
    float A[NL][NL];
    for (int i=0;i<NL;i++)
        for (int j=0;j<=i;j++) A[i][j] = g_G2[b*NL*NL + i*NL + j];
    chol32_serial(A);
    float y[NL];
    float dp = 0.f;
    for (int k=0;k<NL;k++) {
        float s = g_t[b*NL+k];
        for (int j=0;j<k;j++) s -= A[k][j]*y[j];
        y[k] = s/A[k][k];
        dp += y[k]*y[k];
    }
    float sp2 = g_sp2[b], sv2 = g_sv2[b];
    float recon = g_dsq[b]/(2.f*sv2*sv2)
                + dp*(0.5f/(sp2*sp2) - 0.5f/(sv2*sv2))
                + (float)NL*logf(sp2) + (float)(DD-NL)*logf(sv2);
    float latent = 0.5f*g_zn[b] + 0.5f*g_trinv[b];
    out[b] = (recon + latent + g_logdet[b]) / (float)DD;
}

extern "C" void kernel_launch(void* const* d_in, const int* in_sizes, int n_in,
                              void* d_out, int out_size) {
    const float* x      = (const float*)d_in[0];
    const float* eps    = (const float*)d_in[1];
    const float* enc_W1 = (const float*)d_in[2];
    const float* enc_b1 = (const float*)d_in[3];
    const float* enc_W2 = (const float*)d_in[4];
    const float* enc_b2 = (const float*)d_in[5];
    const float* dec_W1 = (const float*)d_in[6];
    const float* dec_b1 = (const float*)d_in[7];
    const float* dec_W2 = (const float*)d_in[8];
    const float* dec_b2 = (const float*)d_in[9];
    const float* sig_W  = (const float*)d_in[10];
    const float* sig_b  = (const float*)d_in[11];
    float* out = (float*)d_out;

    zero_kernel<<<256,256>>>();

    // bf16 weight copies: dec_W2 row-major, enc_W1^T, dec_W2^T
    w2bf_kernel<<<(HH*DD/4)/256,256>>>(dec_W2);
    convT_kernel<0><<<dim3(HH/32, DD/32),256>>>(enc_W1, DD, HH);
    convT_kernel<1><<<dim3(DD/32, HH/32),256>>>(dec_W2, HH, DD);

    // HMMA syrk (upper tiles) + mirror + bf16 C
    syrk_mma_kernel<<<136,256>>>();
    mirror_kernel<<<2080,1024>>>();
    cbf_kernel<<<(HH*HH/4)/256,256>>>();

    // encoder: h1 = x @ enc_W1 (HMMA, split-K12, atomic into zeroed g_h1)
    hmma64_kernel<0,0,0><<<dim3(HH/128,1,12),256>>>(x, DD, HH, DD/12);
    relu_bias_kernel<<<(BB*HH)/256,256>>>(enc_b1);
    z1_kernel<<<BB,256>>>(enc_W2, enc_b2);
    spsv_kernel<<<1,64>>>(sig_W, sig_b);
    sigterm_kernel<<<1,1024>>>(sig_W);

    // m1; T1 = (W1.*m1)@C (HMMA); Prec
    dec_kernel<<<dim3(8,BB),256>>>(dec_W1, dec_b1, 0);
    t_gemm_mma_kernel<<<dim3(16,BB),256>>>(dec_W1, 0);
    g_kernel<<<BB,1024>>>(dec_W1, 0);

    chol_prec_kernel<<<1,64>>>(eps, sig_W, sig_b);

    // decoder at z_s: m2,h2; x_star = h2 @ dec_W2 (HMMA, split-K2, atomic into zeroed g_delta)
    dec_kernel<<<dim3(8,BB),256>>>(dec_W1, dec_b1, 1);
    hmma64_kernel<1,1,1><<<dim3(DD/128,1,2),256>>>(nullptr, HH, DD, HH/2);
    delta_kernel<<<dim3(48,BB),256>>>(x, dec_b2);

    // v = delta @ dec_W2^T (HMMA, split-K12, atomic into zeroed g_v)
    hmma64_kernel<2,2,2><<<dim3(HH/128,1,12),256>>>(nullptr, DD, HH, DD/12);

    // T2 (HMMA), G2, t, final
    t_gemm_mma_kernel<<<dim3(16,BB),256>>>(dec_W1, 1);
    g_kernel<<<BB,1024>>>(dec_W1, 1);
    t_kernel<<<BB,256>>>(dec_W1);
    final_kernel<<<1,64>>>(out);
}